// round 6
// baseline (speedup 1.0000x reference)
#include <cuda_runtime.h>
#include <math.h>

// ---------------------------------------------------------------------------
// Problem constants
// ---------------------------------------------------------------------------
namespace {
constexpr int NTOK   = 196;
constexpr int NBATCH = 8;
constexpr int NN     = NTOK * NTOK;        // 38416
constexpr int MTOT   = NBATCH * NN;        // 307328  (== 2401 * 128)
constexpr int INDIM  = 2048;
constexpr int C0     = 256;
constexpr int C1     = 128;
constexpr int C2     = 64;
constexpr int KH     = 3 * C0;             // 768 (conv1 factorized K)
}

// ---------------------------------------------------------------------------
// tf32 mma / ldmatrix helpers
// ---------------------------------------------------------------------------
__device__ __forceinline__ unsigned cvt_tf32(float f) {
    unsigned r; asm("cvt.rna.tf32.f32 %0, %1;" : "=r"(r) : "f"(f)); return r;
}
__device__ __forceinline__ float tf32f(float f) {
    return __uint_as_float(cvt_tf32(f));
}
__device__ __forceinline__ void mma_tf32(float* d, const unsigned* a, const unsigned* b) {
    asm volatile(
        "mma.sync.aligned.m16n8k8.row.col.f32.tf32.tf32.f32 "
        "{%0,%1,%2,%3}, {%4,%5,%6,%7}, {%8,%9}, {%0,%1,%2,%3};"
        : "+f"(d[0]), "+f"(d[1]), "+f"(d[2]), "+f"(d[3])
        : "r"(a[0]), "r"(a[1]), "r"(a[2]), "r"(a[3]),
          "r"(b[0]), "r"(b[1]));
}
__device__ __forceinline__ unsigned fu(float f) { return __float_as_uint(f); }
__device__ __forceinline__ void ldsm4(unsigned& r0, unsigned& r1, unsigned& r2, unsigned& r3,
                                      unsigned addr) {
    asm volatile("ldmatrix.sync.aligned.m8n8.x4.shared.b16 {%0,%1,%2,%3}, [%4];"
                 : "=r"(r0), "=r"(r1), "=r"(r2), "=r"(r3) : "r"(addr));
}

// ---------------------------------------------------------------------------
// Scratch
// ---------------------------------------------------------------------------
__device__ float g_sub [NBATCH * NTOK * C0];
__device__ float g_s1  [(long long)MTOT * C1];
__device__ float g_s2  [(long long)MTOT * C2];
__device__ float g_H   [(long long)NBATCH * NTOK * KH * C1];   // 617 MB
__device__ float g_L0  [MTOT];
__device__ float g_L1  [MTOT];
__device__ float g_Mc  [MTOT];
__device__ float g_stats[32];

// ---------------------------------------------------------------------------
// Generic guarded tf32 TC GEMM (BN=128), used for projection + aggregation.
// ---------------------------------------------------------------------------
template<bool RELU, bool HASBIAS>
__global__ void __launch_bounds__(256)
gemm_tc(const float* __restrict__ A, const float* __restrict__ B,
        const float* __restrict__ bias, float* __restrict__ C,
        int M, int K, int N, long long sA, long long sB, long long sC)
{
    constexpr int BM = 128, BN = 128, BK = 8;
    constexpr int MT = 2, NT = 8;
    constexpr int AP = BM + 8, BP = BN + 8;

    A += (long long)blockIdx.z * sA;
    B += (long long)blockIdx.z * sB;
    C += (long long)blockIdx.z * sC;

    const int tid  = threadIdx.x;
    const int wid  = tid >> 5, lane = tid & 31;
    const int lr   = lane >> 2, lc = lane & 3;
    const int wm   = (wid % 4) * 32;
    const int wn   = (wid / 4) * 64;
    const int m0   = blockIdx.x * BM;
    const int n0   = blockIdx.y * BN;

    __shared__ __align__(16) float As[2][BK][AP];
    __shared__ __align__(16) float Bs[2][BK][BP];

    const int ar = tid >> 1;
    const int ak = (tid & 1) * 4;
    const int bk = tid >> 5;
    const int bc = (tid & 31) * 4;

    float aReg[4], bReg[4];
    float acc[MT][NT][4];
    #pragma unroll
    for (int mt = 0; mt < MT; mt++)
        #pragma unroll
        for (int nt = 0; nt < NT; nt++)
            #pragma unroll
            for (int c = 0; c < 4; c++) acc[mt][nt][c] = 0.f;

    const int nk = (K + BK - 1) / BK;

    auto loadA = [&](int kt) {
        const int m = m0 + ar;
        const int k = kt * BK + ak;
        if (m < M && (k + 3) < K) {
            const float4 v = *reinterpret_cast<const float4*>(A + (long long)m * K + k);
            aReg[0] = v.x; aReg[1] = v.y; aReg[2] = v.z; aReg[3] = v.w;
        } else {
            #pragma unroll
            for (int c = 0; c < 4; c++)
                aReg[c] = (m < M && (k + c) < K) ? A[(long long)m * K + k + c] : 0.f;
        }
    };
    auto loadB = [&](int kt) {
        const int k = kt * BK + bk;
        if (k < K) {
            const float4 v = *reinterpret_cast<const float4*>(B + (long long)k * N + n0 + bc);
            bReg[0] = v.x; bReg[1] = v.y; bReg[2] = v.z; bReg[3] = v.w;
        } else {
            #pragma unroll
            for (int c = 0; c < 4; c++) bReg[c] = 0.f;
        }
    };
    auto stS = [&](int buf) {
        #pragma unroll
        for (int c = 0; c < 4; c++) As[buf][ak + c][ar] = tf32f(aReg[c]);
        #pragma unroll
        for (int c = 0; c < 4; c++) Bs[buf][bk][bc + c] = tf32f(bReg[c]);
    };

    loadA(0); loadB(0); stS(0);
    __syncthreads();

    for (int kt = 0; kt < nk; ++kt) {
        const int cur = kt & 1;
        if (kt + 1 < nk) { loadA(kt + 1); loadB(kt + 1); }
        unsigned af[MT][4], bf[NT][2];
        #pragma unroll
        for (int mt = 0; mt < MT; mt++) {
            const int r = wm + mt * 16 + lr;
            af[mt][0] = fu(As[cur][lc    ][r]);
            af[mt][1] = fu(As[cur][lc    ][r + 8]);
            af[mt][2] = fu(As[cur][lc + 4][r]);
            af[mt][3] = fu(As[cur][lc + 4][r + 8]);
        }
        #pragma unroll
        for (int nt = 0; nt < NT; nt++) {
            const int n = wn + nt * 8 + lr;
            bf[nt][0] = fu(Bs[cur][lc    ][n]);
            bf[nt][1] = fu(Bs[cur][lc + 4][n]);
        }
        #pragma unroll
        for (int mt = 0; mt < MT; mt++)
            #pragma unroll
            for (int nt = 0; nt < NT; nt++)
                mma_tf32(acc[mt][nt], af[mt], bf[nt]);
        if (kt + 1 < nk) stS(cur ^ 1);
        __syncthreads();
    }

    #pragma unroll
    for (int mt = 0; mt < MT; mt++)
        #pragma unroll
        for (int nt = 0; nt < NT; nt++) {
            const int col = n0 + wn + nt * 8 + 2 * lc;
            #pragma unroll
            for (int h = 0; h < 2; h++) {
                const int m = m0 + wm + mt * 16 + lr + h * 8;
                if (m >= M) continue;
                float v0 = acc[mt][nt][2 * h];
                float v1 = acc[mt][nt][2 * h + 1];
                if constexpr (HASBIAS) { v0 += bias[col]; v1 += bias[col + 1]; }
                if constexpr (RELU)    { v0 = fmaxf(v0, 0.f); v1 = fmaxf(v1, 0.f); }
                *reinterpret_cast<float2*>(C + (long long)m * N + col) = make_float2(v0, v1);
            }
        }
}

// ---------------------------------------------------------------------------
// hbuild_k: H[z][(q,c)][d] = sum_p sub[b,i+p-1,c] * w1[p,q,c,d], tf32-rounded.
// 4 i-values per block amortize W reads; coalesced everywhere.
// ---------------------------------------------------------------------------
__global__ void __launch_bounds__(256)
hbuild_k(const float* __restrict__ sub, const float* __restrict__ W,
         float* __restrict__ H)
{
    constexpr int ZPB = 4;
    __shared__ float sR[ZPB][3 * C0];
    const int z0 = blockIdx.x * ZPB;
    const int tid = threadIdx.x;

    for (int idx = tid; idx < ZPB * 3 * C0; idx += 256) {
        const int zz = idx / (3 * C0);
        const int rem = idx - zz * (3 * C0);
        const int p = rem >> 8, c = rem & 255;
        const int z = z0 + zz;
        const int b = z / NTOK;
        const int i = z - b * NTOK;
        const int ii = i + p - 1;
        sR[zz][rem] = (ii >= 0 && ii < NTOK) ? sub[(b * NTOK + ii) * C0 + c] : 0.f;
    }
    __syncthreads();

    const int d = tid & 127;
    const int half = tid >> 7;
    for (int r = half; r < KH; r += 2) {
        const int q = r >> 8, c = r & 255;
        const float w0 = W[((size_t)(q * C0 + c)) * C1 + d];
        const float w1v = W[((size_t)((3 + q) * C0 + c)) * C1 + d];
        const float w2v = W[((size_t)((6 + q) * C0 + c)) * C1 + d];
        #pragma unroll
        for (int zz = 0; zz < ZPB; zz++) {
            float h = sR[zz][c] * w0;
            h = fmaf(sR[zz][C0 + c], w1v, h);
            h = fmaf(sR[zz][2 * C0 + c], w2v, h);
            H[((long long)(z0 + zz) * KH + r) * C1 + d] = tf32f(h);
        }
    }
}

// ---------------------------------------------------------------------------
// pair4_k: relu(pair @ w01 + b01). 128x128x256, 4 warps, warp tile 64x64.
// ---------------------------------------------------------------------------
__global__ void __launch_bounds__(128)
pair4_k(const float* __restrict__ sub, const float* __restrict__ W,
        const float* __restrict__ bias, float* __restrict__ C)
{
    constexpr int BM = 128, BN = 128, MT = 4, NT = 8;
    constexpr int nk = C0 / 8;   // 32

    __shared__ __align__(16) float As[2][BM][12];
    __shared__ __align__(16) float Bs[2][BN][12];

    const int tid = threadIdx.x, lane = tid & 31, wid = tid >> 5;
    const int lr = lane >> 2, lc = lane & 3;
    const int wm = (wid & 1) * 64;
    const int wn = (wid >> 1) * 64;
    const int m0 = blockIdx.x * BM;

    const int m  = m0 + tid;
    const int pb = m / NN;
    const int pr = m - pb * NN;
    const int pi = pr / NTOK;
    const int pj = pr - pi * NTOK;
    const float* rowI = sub + (long long)(pb * NTOK + pi) * C0;
    const float* rowJ = sub + (long long)(pb * NTOK + pj) * C0;

    const unsigned aB = (unsigned)__cvta_generic_to_shared(&As[0][0][0]);
    const unsigned bB = (unsigned)__cvta_generic_to_shared(&Bs[0][0][0]);
    const unsigned aOff = ((lane & 7) + ((lane & 8) ? 8 : 0)) * 48 + ((lane & 16) ? 16 : 0);
    const unsigned bOff = ((lane & 7) + ((lane & 16) ? 8 : 0)) * 48 + ((lane & 8) ? 16 : 0);

    float aReg[8], bReg[8];
    float acc[MT][NT][4];
    #pragma unroll
    for (int mt = 0; mt < MT; mt++)
        #pragma unroll
        for (int nt = 0; nt < NT; nt++)
            #pragma unroll
            for (int c = 0; c < 4; c++) acc[mt][nt][c] = 0.f;

    auto loadA = [&](int kt) {
        const int k = kt * 8;
        const float4 a0 = *reinterpret_cast<const float4*>(rowI + k);
        const float4 a1 = *reinterpret_cast<const float4*>(rowI + k + 4);
        const float4 b0 = *reinterpret_cast<const float4*>(rowJ + k);
        const float4 b1 = *reinterpret_cast<const float4*>(rowJ + k + 4);
        aReg[0] = a0.x * b0.x; aReg[1] = a0.y * b0.y; aReg[2] = a0.z * b0.z; aReg[3] = a0.w * b0.w;
        aReg[4] = a1.x * b1.x; aReg[5] = a1.y * b1.y; aReg[6] = a1.z * b1.z; aReg[7] = a1.w * b1.w;
    };
    auto loadB = [&](int kt) {
        const int k = kt * 8;
        #pragma unroll
        for (int kk = 0; kk < 8; kk++) bReg[kk] = W[(k + kk) * C1 + tid];
    };
    auto stS = [&](int buf) {
        float* ap = &As[buf][tid][0];
        *reinterpret_cast<float4*>(ap) =
            make_float4(tf32f(aReg[0]), tf32f(aReg[1]), tf32f(aReg[2]), tf32f(aReg[3]));
        *reinterpret_cast<float4*>(ap + 4) =
            make_float4(tf32f(aReg[4]), tf32f(aReg[5]), tf32f(aReg[6]), tf32f(aReg[7]));
        float* bp = &Bs[buf][tid][0];
        *reinterpret_cast<float4*>(bp) =
            make_float4(tf32f(bReg[0]), tf32f(bReg[1]), tf32f(bReg[2]), tf32f(bReg[3]));
        *reinterpret_cast<float4*>(bp + 4) =
            make_float4(tf32f(bReg[4]), tf32f(bReg[5]), tf32f(bReg[6]), tf32f(bReg[7]));
    };

    loadA(0); loadB(0); stS(0);
    __syncthreads();

    for (int kt = 0; kt < nk; ++kt) {
        const int cur = kt & 1;
        if (kt + 1 < nk) { loadA(kt + 1); loadB(kt + 1); }
        const unsigned aAddr = aB + cur * (BM * 48) + wm * 48 + aOff;
        const unsigned bAddr = bB + cur * (BN * 48) + wn * 48 + bOff;
        unsigned af[MT][4], bf[NT][2];
        #pragma unroll
        for (int mt = 0; mt < MT; mt++)
            ldsm4(af[mt][0], af[mt][1], af[mt][2], af[mt][3], aAddr + mt * 768);
        #pragma unroll
        for (int g = 0; g < NT / 2; g++) {
            unsigned r0, r1, r2, r3;
            ldsm4(r0, r1, r2, r3, bAddr + g * 768);
            bf[2 * g][0] = r0; bf[2 * g][1] = r1;
            bf[2 * g + 1][0] = r2; bf[2 * g + 1][1] = r3;
        }
        #pragma unroll
        for (int mt = 0; mt < MT; mt++)
            #pragma unroll
            for (int nt = 0; nt < NT; nt++)
                mma_tf32(acc[mt][nt], af[mt], bf[nt]);
        if (kt + 1 < nk) stS(cur ^ 1);
        __syncthreads();
    }

    #pragma unroll
    for (int mt = 0; mt < MT; mt++)
        #pragma unroll
        for (int nt = 0; nt < NT; nt++) {
            const int col = wn + nt * 8 + 2 * lc;
            #pragma unroll
            for (int h = 0; h < 2; h++) {
                const long long row = m0 + wm + mt * 16 + lr + h * 8;
                float v0 = fmaxf(acc[mt][nt][2 * h]     + bias[col],     0.f);
                float v1 = fmaxf(acc[mt][nt][2 * h + 1] + bias[col + 1], 0.f);
                *reinterpret_cast<float2*>(C + row * C1 + col) = make_float2(v0, v1);
            }
        }
}

// ---------------------------------------------------------------------------
// conv1g_k: conv1 GEMM consuming precomputed H. One block per (b,i); BM=256
// covers all j; 8 warps 4x2, warp tile 64x64, K=768.
// ---------------------------------------------------------------------------
__global__ void __launch_bounds__(256)
conv1g_k(const float* __restrict__ sub, const float* __restrict__ H,
         const float* __restrict__ bias, float* __restrict__ Out)
{
    constexpr int BM = 256, BN = 128, MT = 4, NT = 8;
    constexpr int nk = KH / 8;   // 96

    __shared__ __align__(16) float As[2][BM][12];
    __shared__ __align__(16) float Bs[2][BN][12];

    const int tid = threadIdx.x, lane = tid & 31, wid = tid >> 5;
    const int lr = lane >> 2, lc = lane & 3;
    const int wm = (wid & 3) * 64;
    const int wn = (wid >> 2) * 64;
    const int z  = blockIdx.x;          // b*196 + i
    const int b  = z / NTOK;
    const int i  = z - b * NTOK;
    const float* subB = sub + (long long)b * NTOK * C0;
    const float* Hz   = H + (long long)z * KH * C1;

    const unsigned aB = (unsigned)__cvta_generic_to_shared(&As[0][0][0]);
    const unsigned bB = (unsigned)__cvta_generic_to_shared(&Bs[0][0][0]);
    const unsigned aOff = ((lane & 7) + ((lane & 8) ? 8 : 0)) * 48 + ((lane & 16) ? 16 : 0);
    const unsigned bOff = ((lane & 7) + ((lane & 16) ? 8 : 0)) * 48 + ((lane & 8) ? 16 : 0);

    float aReg[8], bReg[8];
    float acc[MT][NT][4];
    #pragma unroll
    for (int mt = 0; mt < MT; mt++)
        #pragma unroll
        for (int nt = 0; nt < NT; nt++)
            #pragma unroll
            for (int c = 0; c < 4; c++) acc[mt][nt][c] = 0.f;

    auto loadA = [&](int kt) {
        const int k = kt * 8;
        const int q = k >> 8;
        const int c = k & 255;
        const int jj = tid + q - 1;          // row j = tid
        if (tid < NTOK && jj >= 0 && jj < NTOK) {
            const float4 v0 = *reinterpret_cast<const float4*>(subB + jj * C0 + c);
            const float4 v1 = *reinterpret_cast<const float4*>(subB + jj * C0 + c + 4);
            aReg[0] = v0.x; aReg[1] = v0.y; aReg[2] = v0.z; aReg[3] = v0.w;
            aReg[4] = v1.x; aReg[5] = v1.y; aReg[6] = v1.z; aReg[7] = v1.w;
        } else {
            #pragma unroll
            for (int c2 = 0; c2 < 8; c2++) aReg[c2] = 0.f;
        }
    };
    auto loadB = [&](int kt) {               // tid < 128 (d = tid)
        const float* Hp = Hz + (long long)(kt * 8) * C1 + tid;
        #pragma unroll
        for (int kk = 0; kk < 8; kk++) bReg[kk] = Hp[kk * C1];
    };
    auto stS = [&](int buf) {
        float* ap = &As[buf][tid][0];
        *reinterpret_cast<float4*>(ap) =
            make_float4(tf32f(aReg[0]), tf32f(aReg[1]), tf32f(aReg[2]), tf32f(aReg[3]));
        *reinterpret_cast<float4*>(ap + 4) =
            make_float4(tf32f(aReg[4]), tf32f(aReg[5]), tf32f(aReg[6]), tf32f(aReg[7]));
        if (tid < BN) {
            float* bp = &Bs[buf][tid][0];     // H already tf32-rounded
            *reinterpret_cast<float4*>(bp) =
                make_float4(bReg[0], bReg[1], bReg[2], bReg[3]);
            *reinterpret_cast<float4*>(bp + 4) =
                make_float4(bReg[4], bReg[5], bReg[6], bReg[7]);
        }
    };

    loadA(0); if (tid < BN) loadB(0); stS(0);
    __syncthreads();

    for (int kt = 0; kt < nk; ++kt) {
        const int cur = kt & 1;
        if (kt + 1 < nk) { loadA(kt + 1); if (tid < BN) loadB(kt + 1); }
        const unsigned aAddr = aB + cur * (BM * 48) + wm * 48 + aOff;
        const unsigned bAddr = bB + cur * (BN * 48) + wn * 48 + bOff;
        unsigned af[MT][4], bf[NT][2];
        #pragma unroll
        for (int mt = 0; mt < MT; mt++)
            ldsm4(af[mt][0], af[mt][1], af[mt][2], af[mt][3], aAddr + mt * 768);
        #pragma unroll
        for (int g = 0; g < NT / 2; g++) {
            unsigned r0, r1, r2, r3;
            ldsm4(r0, r1, r2, r3, bAddr + g * 768);
            bf[2 * g][0] = r0; bf[2 * g][1] = r1;
            bf[2 * g + 1][0] = r2; bf[2 * g + 1][1] = r3;
        }
        #pragma unroll
        for (int mt = 0; mt < MT; mt++)
            #pragma unroll
            for (int nt = 0; nt < NT; nt++)
                mma_tf32(acc[mt][nt], af[mt], bf[nt]);
        if (kt + 1 < nk) stS(cur ^ 1);
        __syncthreads();
    }

    #pragma unroll
    for (int mt = 0; mt < MT; mt++)
        #pragma unroll
        for (int nt = 0; nt < NT; nt++) {
            const int col = wn + nt * 8 + 2 * lc;
            #pragma unroll
            for (int h = 0; h < 2; h++) {
                const int j = wm + mt * 16 + lr + h * 8;
                if (j >= NTOK) continue;
                const long long mm = (long long)b * NN + (long long)i * NTOK + j;
                float v0 = fmaxf(acc[mt][nt][2 * h]     + bias[col],     0.f);
                float v1 = fmaxf(acc[mt][nt][2 * h + 1] + bias[col + 1], 0.f);
                *reinterpret_cast<float2*>(Out + mm * C1 + col) = make_float2(v0, v1);
            }
        }
}

// ---------------------------------------------------------------------------
// conv24_k: conv2 (128->64, W-dil=2) as single K=1152 implicit GEMM.
// ---------------------------------------------------------------------------
__global__ void __launch_bounds__(128)
conv24_k(const float* __restrict__ In, const float* __restrict__ W,
         const float* __restrict__ bias, float* __restrict__ Out)
{
    constexpr int BM = 128, BN = 64, MT = 4, NT = 4;
    constexpr int nk = (9 * C1) / 8;   // 144

    __shared__ __align__(16) float As[2][BM][12];
    __shared__ __align__(16) float Bs[2][BN][12];
    __shared__ int rowbase[9][BM];

    const int tid = threadIdx.x, lane = tid & 31, wid = tid >> 5;
    const int lr = lane >> 2, lc = lane & 3;
    const int wm = (wid & 1) * 64;
    const int wn = (wid >> 1) * 32;
    const int m0 = blockIdx.x * BM;

    {
        const int m = m0 + tid;
        const int pb = m / NN;
        const int r = m - pb * NN;
        const int pi = r / NTOK;
        const int pj = r - pi * NTOK;
        #pragma unroll
        for (int tap = 0; tap < 9; tap++) {
            const int p = tap / 3 - 1, q = tap % 3 - 1;
            const int ii = pi + p, jj = pj + q * 2;
            rowbase[tap][tid] = (ii >= 0 && ii < NTOK && jj >= 0 && jj < NTOK)
                              ? ((pb * NTOK + ii) * NTOK + jj) * C1 : -1;
        }
    }
    __syncthreads();

    const unsigned aB = (unsigned)__cvta_generic_to_shared(&As[0][0][0]);
    const unsigned bB = (unsigned)__cvta_generic_to_shared(&Bs[0][0][0]);
    const unsigned aOff = ((lane & 7) + ((lane & 8) ? 8 : 0)) * 48 + ((lane & 16) ? 16 : 0);
    const unsigned bOff = ((lane & 7) + ((lane & 16) ? 8 : 0)) * 48 + ((lane & 8) ? 16 : 0);

    float aReg[8], bReg[8];
    float acc[MT][NT][4];
    #pragma unroll
    for (int mt = 0; mt < MT; mt++)
        #pragma unroll
        for (int nt = 0; nt < NT; nt++)
            #pragma unroll
            for (int c = 0; c < 4; c++) acc[mt][nt][c] = 0.f;

    auto loadA = [&](int kt) {
        const int k = kt * 8;
        const int tap = k >> 7;
        const int c = k & 127;
        const int base = rowbase[tap][tid];
        if (base >= 0) {
            const float4 v0 = *reinterpret_cast<const float4*>(In + base + c);
            const float4 v1 = *reinterpret_cast<const float4*>(In + base + c + 4);
            aReg[0] = v0.x; aReg[1] = v0.y; aReg[2] = v0.z; aReg[3] = v0.w;
            aReg[4] = v1.x; aReg[5] = v1.y; aReg[6] = v1.z; aReg[7] = v1.w;
        } else {
            #pragma unroll
            for (int c2 = 0; c2 < 8; c2++) aReg[c2] = 0.f;
        }
    };
    auto loadB = [&](int kt) {          // tid < 64, d = tid
        const int k = kt * 8;
        const int tap = k >> 7;
        const int c = k & 127;
        #pragma unroll
        for (int kk = 0; kk < 8; kk++)
            bReg[kk] = W[((size_t)(tap * C1 + c + kk)) * C2 + tid];
    };
    auto stS = [&](int buf) {
        float* ap = &As[buf][tid][0];
        *reinterpret_cast<float4*>(ap) =
            make_float4(tf32f(aReg[0]), tf32f(aReg[1]), tf32f(aReg[2]), tf32f(aReg[3]));
        *reinterpret_cast<float4*>(ap + 4) =
            make_float4(tf32f(aReg[4]), tf32f(aReg[5]), tf32f(aReg[6]), tf32f(aReg[7]));
        if (tid < BN) {
            float* bp = &Bs[buf][tid][0];
            *reinterpret_cast<float4*>(bp) =
                make_float4(tf32f(bReg[0]), tf32f(bReg[1]), tf32f(bReg[2]), tf32f(bReg[3]));
            *reinterpret_cast<float4*>(bp + 4) =
                make_float4(tf32f(bReg[4]), tf32f(bReg[5]), tf32f(bReg[6]), tf32f(bReg[7]));
        }
    };

    loadA(0); if (tid < BN) loadB(0); stS(0);
    __syncthreads();

    for (int kt = 0; kt < nk; ++kt) {
        const int cur = kt & 1;
        if (kt + 1 < nk) { loadA(kt + 1); if (tid < BN) loadB(kt + 1); }
        const unsigned aAddr = aB + cur * (BM * 48) + wm * 48 + aOff;
        const unsigned bAddr = bB + cur * (BN * 48) + wn * 48 + bOff;
        unsigned af[MT][4], bf[NT][2];
        #pragma unroll
        for (int mt = 0; mt < MT; mt++)
            ldsm4(af[mt][0], af[mt][1], af[mt][2], af[mt][3], aAddr + mt * 768);
        #pragma unroll
        for (int g = 0; g < NT / 2; g++) {
            unsigned r0, r1, r2, r3;
            ldsm4(r0, r1, r2, r3, bAddr + g * 768);
            bf[2 * g][0] = r0; bf[2 * g][1] = r1;
            bf[2 * g + 1][0] = r2; bf[2 * g + 1][1] = r3;
        }
        #pragma unroll
        for (int mt = 0; mt < MT; mt++)
            #pragma unroll
            for (int nt = 0; nt < NT; nt++)
                mma_tf32(acc[mt][nt], af[mt], bf[nt]);
        if (kt + 1 < nk) stS(cur ^ 1);
        __syncthreads();
    }

    #pragma unroll
    for (int mt = 0; mt < MT; mt++)
        #pragma unroll
        for (int nt = 0; nt < NT; nt++) {
            const int col = wn + nt * 8 + 2 * lc;
            #pragma unroll
            for (int h = 0; h < 2; h++) {
                const long long row = m0 + wm + mt * 16 + lr + h * 8;
                float v0 = fmaxf(acc[mt][nt][2 * h]     + bias[col],     0.f);
                float v1 = fmaxf(acc[mt][nt][2 * h + 1] + bias[col + 1], 0.f);
                *reinterpret_cast<float2*>(Out + row * C2 + col) = make_float2(v0, v1);
            }
        }
}

// ---------------------------------------------------------------------------
// gemm64L0_k: L0 = relu( relu(s1 @ w02 + b02) . w03 + b03 ). 8 warps 16x64.
// ---------------------------------------------------------------------------
__global__ void __launch_bounds__(256)
gemm64L0_k(const float* __restrict__ A, const float* __restrict__ B,
           const float* __restrict__ bias, const float* __restrict__ w03,
           const float* __restrict__ b03, float* __restrict__ L0)
{
    constexpr int BM = 128, BN = 64, BK = 8;
    constexpr int NT = 8;
    constexpr int AP = BM + 8, BP = BN + 8;
    constexpr int K = C1, N = C2;
    constexpr int nk = K / BK;  // 16

    const int tid  = threadIdx.x;
    const int wid  = tid >> 5, lane = tid & 31;
    const int lr   = lane >> 2, lc = lane & 3;
    const int wm   = wid * 16;
    const int m0   = blockIdx.x * BM;

    __shared__ __align__(16) float As[2][BK][AP];
    __shared__ __align__(16) float Bs[2][BK][BP];

    const int ar = tid >> 1;
    const int ak = (tid & 1) * 4;
    const int bk = tid >> 5;
    const int bc = (tid & 31) * 2;

    float aReg[4], bReg[2];
    float acc[NT][4];
    #pragma unroll
    for (int nt = 0; nt < NT; nt++)
        #pragma unroll
        for (int c = 0; c < 4; c++) acc[nt][c] = 0.f;

    auto loadA = [&](int kt) {
        const int k = kt * BK + ak;
        const float4 v = *reinterpret_cast<const float4*>(A + (long long)(m0 + ar) * K + k);
        aReg[0] = v.x; aReg[1] = v.y; aReg[2] = v.z; aReg[3] = v.w;
    };
    auto loadB = [&](int kt) {
        const int k = kt * BK + bk;
        const float2 v = *reinterpret_cast<const float2*>(B + (long long)k * N + bc);
        bReg[0] = v.x; bReg[1] = v.y;
    };
    auto stS = [&](int buf) {
        #pragma unroll
        for (int c = 0; c < 4; c++) As[buf][ak + c][ar] = tf32f(aReg[c]);
        #pragma unroll
        for (int c = 0; c < 2; c++) Bs[buf][bk][bc + c] = tf32f(bReg[c]);
    };

    loadA(0); loadB(0); stS(0);
    __syncthreads();

    for (int kt = 0; kt < nk; ++kt) {
        const int cur = kt & 1;
        if (kt + 1 < nk) { loadA(kt + 1); loadB(kt + 1); }
        unsigned af[4], bf[NT][2];
        {
            const int r = wm + lr;
            af[0] = fu(As[cur][lc    ][r]);
            af[1] = fu(As[cur][lc    ][r + 8]);
            af[2] = fu(As[cur][lc + 4][r]);
            af[3] = fu(As[cur][lc + 4][r + 8]);
        }
        #pragma unroll
        for (int nt = 0; nt < NT; nt++) {
            const int n = nt * 8 + lr;
            bf[nt][0] = fu(Bs[cur][lc    ][n]);
            bf[nt][1] = fu(Bs[cur][lc + 4][n]);
        }
        #pragma unroll
        for (int nt = 0; nt < NT; nt++)
            mma_tf32(acc[nt], af, bf[nt]);
        if (kt + 1 < nk) stS(cur ^ 1);
        __syncthreads();
    }

    float part0 = 0.f, part1 = 0.f;
    #pragma unroll
    for (int nt = 0; nt < NT; nt++) {
        const int col = nt * 8 + 2 * lc;
        const float w0 = w03[col], w1v = w03[col + 1];
        part0 += fmaxf(acc[nt][0] + bias[col], 0.f) * w0
               + fmaxf(acc[nt][1] + bias[col + 1], 0.f) * w1v;
        part1 += fmaxf(acc[nt][2] + bias[col], 0.f) * w0
               + fmaxf(acc[nt][3] + bias[col + 1], 0.f) * w1v;
    }
    part0 += __shfl_xor_sync(0xffffffffu, part0, 1);
    part0 += __shfl_xor_sync(0xffffffffu, part0, 2);
    part1 += __shfl_xor_sync(0xffffffffu, part1, 1);
    part1 += __shfl_xor_sync(0xffffffffu, part1, 2);
    if (lc == 0) {
        L0[m0 + wm + lr]     = fmaxf(part0 + b03[0], 0.f);
        L0[m0 + wm + lr + 8] = fmaxf(part1 + b03[0], 0.f);
    }
}

// ---------------------------------------------------------------------------
// Last conv (64 -> 1, dil 4): one warp per output pixel.
// ---------------------------------------------------------------------------
template<int CIN, int DILW>
__global__ void convlast_k(const float* __restrict__ In, const float* __restrict__ W,
                           const float* __restrict__ bias, float* __restrict__ Out)
{
    const int lane = threadIdx.x & 31;
    const int wp   = threadIdx.x >> 5;
    const int m    = blockIdx.x * 8 + wp;
    const int b = m / NN;
    const int r = m - b * NN;
    const int i = r / NTOK;
    const int j = r - i * NTOK;
    float acc = 0.f;
    #pragma unroll
    for (int tap = 0; tap < 9; ++tap) {
        const int p = tap / 3 - 1, q = tap % 3 - 1;
        const int ii = i + p, jj = j + q * DILW;
        if (ii >= 0 && ii < NTOK && jj >= 0 && jj < NTOK) {
            const float* src = In + (long long)((b * NTOK + ii) * NTOK + jj) * CIN;
            const float* w   = W + tap * CIN;
            acc = fmaf(src[lane],      w[lane],      acc);
            acc = fmaf(src[lane + 32], w[lane + 32], acc);
        }
    }
    #pragma unroll
    for (int off = 16; off; off >>= 1) acc += __shfl_xor_sync(0xffffffffu, acc, off);
    if (lane == 0) Out[m] = fmaxf(acc + bias[0], 0.f);
}

// softmax stats over symmetrized logits, per batch
__global__ void smax_stats_k()
{
    const int b = blockIdx.x;
    const float* Lb = (blockIdx.y ? g_L1 : g_L0) + b * NN;
    __shared__ float red[256];
    const int tid = threadIdx.x;
    float mx = -1e30f;
    for (int idx = tid; idx < NN; idx += 256) {
        const int i = idx / NTOK, j = idx - (idx / NTOK) * NTOK;
        mx = fmaxf(mx, Lb[idx] + Lb[j * NTOK + i]);
    }
    red[tid] = mx; __syncthreads();
    for (int s = 128; s; s >>= 1) {
        if (tid < s) red[tid] = fmaxf(red[tid], red[tid + s]);
        __syncthreads();
    }
    mx = red[0]; __syncthreads();
    float sum = 0.f;
    for (int idx = tid; idx < NN; idx += 256) {
        const int i = idx / NTOK, j = idx - (idx / NTOK) * NTOK;
        sum += expf(Lb[idx] + Lb[j * NTOK + i] - mx);
    }
    red[tid] = sum; __syncthreads();
    for (int s = 128; s; s >>= 1) {
        if (tid < s) red[tid] += red[tid + s];
        __syncthreads();
    }
    if (tid == 0) {
        g_stats[(blockIdx.y * 8 + b) * 2]     = mx;
        g_stats[(blockIdx.y * 8 + b) * 2 + 1] = red[0];
    }
}

// Mc = 0.5 * (softmax0 + softmax1)
__global__ void combine_k()
{
    const int idx = blockIdx.x * 256 + threadIdx.x;
    if (idx >= MTOT) return;
    const int b = idx / NN;
    const int r = idx - b * NN;
    const int i = r / NTOK;
    const int j = r - i * NTOK;
    const int t = b * NN + j * NTOK + i;
    const float s0 = g_L0[idx] + g_L0[t];
    const float s1 = g_L1[idx] + g_L1[t];
    const float m0 = g_stats[b * 2],      z0 = g_stats[b * 2 + 1];
    const float m1 = g_stats[16 + b * 2], z1 = g_stats[16 + b * 2 + 1];
    g_Mc[idx] = 0.5f * (expf(s0 - m0) / z0 + expf(s1 - m1) / z1);
}

// ---------------------------------------------------------------------------
extern "C" void kernel_launch(void* const* d_in, const int* in_sizes, int n_in,
                              void* d_out, int out_size)
{
    (void)in_sizes; (void)n_in; (void)out_size;
    const float* x     = (const float*)d_in[0];
    const float* w_prj = (const float*)d_in[1];
    const float* b_prj = (const float*)d_in[2];
    const float* w01   = (const float*)d_in[3];
    const float* b01   = (const float*)d_in[4];
    const float* w02   = (const float*)d_in[5];
    const float* b02   = (const float*)d_in[6];
    const float* w03   = (const float*)d_in[7];
    const float* b03   = (const float*)d_in[8];
    const float* w1    = (const float*)d_in[9];
    const float* b1    = (const float*)d_in[10];
    const float* w2    = (const float*)d_in[11];
    const float* b2    = (const float*)d_in[12];
    const float* w3    = (const float*)d_in[13];
    const float* b3    = (const float*)d_in[14];
    float* out = (float*)d_out;

    float *sub, *s1, *s2, *H, *L0, *L1, *Mc;
    cudaGetSymbolAddress((void**)&sub,  g_sub);
    cudaGetSymbolAddress((void**)&s1,   g_s1);
    cudaGetSymbolAddress((void**)&s2,   g_s2);
    cudaGetSymbolAddress((void**)&H,    g_H);
    cudaGetSymbolAddress((void**)&L0,   g_L0);
    cudaGetSymbolAddress((void**)&L1,   g_L1);
    cudaGetSymbolAddress((void**)&Mc,   g_Mc);

    // 1. projection
    gemm_tc<false, true><<<dim3(13, 2, 1), 256>>>(
        x, w_prj, b_prj, sub, NBATCH * NTOK, INDIM, C0, 0, 0, 0);

    // 2. branch 0
    pair4_k<<<MTOT / 128, 128>>>(sub, w01, b01, s1);
    gemm64L0_k<<<MTOT / 128, 256>>>(s1, w02, b02, w03, b03, L0);

    // 3. branch 1: build H, then GEMM conv1, then conv2/conv3
    hbuild_k<<<NBATCH * NTOK / 4, 256>>>(sub, w1, H);
    conv1g_k<<<NBATCH * NTOK, 256>>>(sub, H, b1, s1);
    conv24_k<<<MTOT / 128, 128>>>(s1, w2, b2, s2);
    convlast_k<64, 4><<<MTOT / 8, 256>>>(s2, w3, b3, L1);

    // 4. softmax + combine
    smax_stats_k<<<dim3(8, 2), 256>>>();
    combine_k<<<(MTOT + 255) / 256, 256>>>();

    // 5. aggregation
    gemm_tc<false, false><<<dim3(2, 16, 8), 256>>>(
        Mc, x, nullptr, out, NTOK, NTOK, INDIM,
        (long long)NN, (long long)NTOK * INDIM, (long long)NTOK * INDIM);
}

// round 10
// speedup vs baseline: 1.0207x; 1.0207x over previous
#include <cuda_runtime.h>
#include <math.h>

// ---------------------------------------------------------------------------
// Problem constants
// ---------------------------------------------------------------------------
namespace {
constexpr int NTOK   = 196;
constexpr int NBATCH = 8;
constexpr int NN     = NTOK * NTOK;        // 38416
constexpr int MTOT   = NBATCH * NN;        // 307328  (== 2401 * 128)
constexpr int INDIM  = 2048;
constexpr int C0     = 256;
constexpr int C1     = 128;
constexpr int C2     = 64;
constexpr int KH     = 3 * C0;             // 768
}

// ---------------------------------------------------------------------------
// tf32 mma / ldmatrix helpers
// ---------------------------------------------------------------------------
__device__ __forceinline__ unsigned cvt_tf32(float f) {
    unsigned r; asm("cvt.rna.tf32.f32 %0, %1;" : "=r"(r) : "f"(f)); return r;
}
__device__ __forceinline__ float tf32f(float f) {
    return __uint_as_float(cvt_tf32(f));
}
__device__ __forceinline__ void mma_tf32(float* d, const unsigned* a, const unsigned* b) {
    asm volatile(
        "mma.sync.aligned.m16n8k8.row.col.f32.tf32.tf32.f32 "
        "{%0,%1,%2,%3}, {%4,%5,%6,%7}, {%8,%9}, {%0,%1,%2,%3};"
        : "+f"(d[0]), "+f"(d[1]), "+f"(d[2]), "+f"(d[3])
        : "r"(a[0]), "r"(a[1]), "r"(a[2]), "r"(a[3]),
          "r"(b[0]), "r"(b[1]));
}
__device__ __forceinline__ unsigned fu(float f) { return __float_as_uint(f); }
__device__ __forceinline__ void ldsm4(unsigned& r0, unsigned& r1, unsigned& r2, unsigned& r3,
                                      unsigned addr) {
    asm volatile("ldmatrix.sync.aligned.m8n8.x4.shared.b16 {%0,%1,%2,%3}, [%4];"
                 : "=r"(r0), "=r"(r1), "=r"(r2), "=r"(r3) : "r"(addr));
}

// ---------------------------------------------------------------------------
// Scratch
// ---------------------------------------------------------------------------
__device__ float g_sub [NBATCH * NTOK * C0];
__device__ float g_s1  [(long long)MTOT * C1];
__device__ float g_s2  [(long long)MTOT * C2];
__device__ float g_L0  [MTOT];
__device__ float g_L1  [MTOT];
__device__ float g_Mc  [MTOT];
__device__ float g_stats[32];

// ---------------------------------------------------------------------------
// Generic guarded tf32 TC GEMM (BN=128): projection + aggregation.
// ---------------------------------------------------------------------------
template<bool RELU, bool HASBIAS>
__global__ void __launch_bounds__(256)
gemm_tc(const float* __restrict__ A, const float* __restrict__ B,
        const float* __restrict__ bias, float* __restrict__ C,
        int M, int K, int N, long long sA, long long sB, long long sC)
{
    constexpr int BM = 128, BN = 128, BK = 8;
    constexpr int MT = 2, NT = 8;
    constexpr int AP = BM + 8, BP = BN + 8;

    A += (long long)blockIdx.z * sA;
    B += (long long)blockIdx.z * sB;
    C += (long long)blockIdx.z * sC;

    const int tid  = threadIdx.x;
    const int wid  = tid >> 5, lane = tid & 31;
    const int lr   = lane >> 2, lc = lane & 3;
    const int wm   = (wid % 4) * 32;
    const int wn   = (wid / 4) * 64;
    const int m0   = blockIdx.x * BM;
    const int n0   = blockIdx.y * BN;

    __shared__ __align__(16) float As[2][BK][AP];
    __shared__ __align__(16) float Bs[2][BK][BP];

    const int ar = tid >> 1;
    const int ak = (tid & 1) * 4;
    const int bk = tid >> 5;
    const int bc = (tid & 31) * 4;

    float aReg[4], bReg[4];
    float acc[MT][NT][4];
    #pragma unroll
    for (int mt = 0; mt < MT; mt++)
        #pragma unroll
        for (int nt = 0; nt < NT; nt++)
            #pragma unroll
            for (int c = 0; c < 4; c++) acc[mt][nt][c] = 0.f;

    const int nk = (K + BK - 1) / BK;

    auto loadA = [&](int kt) {
        const int m = m0 + ar;
        const int k = kt * BK + ak;
        if (m < M && (k + 3) < K) {
            const float4 v = *reinterpret_cast<const float4*>(A + (long long)m * K + k);
            aReg[0] = v.x; aReg[1] = v.y; aReg[2] = v.z; aReg[3] = v.w;
        } else {
            #pragma unroll
            for (int c = 0; c < 4; c++)
                aReg[c] = (m < M && (k + c) < K) ? A[(long long)m * K + k + c] : 0.f;
        }
    };
    auto loadB = [&](int kt) {
        const int k = kt * BK + bk;
        if (k < K) {
            const float4 v = *reinterpret_cast<const float4*>(B + (long long)k * N + n0 + bc);
            bReg[0] = v.x; bReg[1] = v.y; bReg[2] = v.z; bReg[3] = v.w;
        } else {
            #pragma unroll
            for (int c = 0; c < 4; c++) bReg[c] = 0.f;
        }
    };
    auto stS = [&](int buf) {
        #pragma unroll
        for (int c = 0; c < 4; c++) As[buf][ak + c][ar] = tf32f(aReg[c]);
        #pragma unroll
        for (int c = 0; c < 4; c++) Bs[buf][bk][bc + c] = tf32f(bReg[c]);
    };

    loadA(0); loadB(0); stS(0);
    __syncthreads();

    for (int kt = 0; kt < nk; ++kt) {
        const int cur = kt & 1;
        if (kt + 1 < nk) { loadA(kt + 1); loadB(kt + 1); }
        unsigned af[MT][4], bf[NT][2];
        #pragma unroll
        for (int mt = 0; mt < MT; mt++) {
            const int r = wm + mt * 16 + lr;
            af[mt][0] = fu(As[cur][lc    ][r]);
            af[mt][1] = fu(As[cur][lc    ][r + 8]);
            af[mt][2] = fu(As[cur][lc + 4][r]);
            af[mt][3] = fu(As[cur][lc + 4][r + 8]);
        }
        #pragma unroll
        for (int nt = 0; nt < NT; nt++) {
            const int n = wn + nt * 8 + lr;
            bf[nt][0] = fu(Bs[cur][lc    ][n]);
            bf[nt][1] = fu(Bs[cur][lc + 4][n]);
        }
        #pragma unroll
        for (int mt = 0; mt < MT; mt++)
            #pragma unroll
            for (int nt = 0; nt < NT; nt++)
                mma_tf32(acc[mt][nt], af[mt], bf[nt]);
        if (kt + 1 < nk) stS(cur ^ 1);
        __syncthreads();
    }

    #pragma unroll
    for (int mt = 0; mt < MT; mt++)
        #pragma unroll
        for (int nt = 0; nt < NT; nt++) {
            const int col = n0 + wn + nt * 8 + 2 * lc;
            #pragma unroll
            for (int h = 0; h < 2; h++) {
                const int m = m0 + wm + mt * 16 + lr + h * 8;
                if (m >= M) continue;
                float v0 = acc[mt][nt][2 * h];
                float v1 = acc[mt][nt][2 * h + 1];
                if constexpr (HASBIAS) { v0 += bias[col]; v1 += bias[col + 1]; }
                if constexpr (RELU)    { v0 = fmaxf(v0, 0.f); v1 = fmaxf(v1, 0.f); }
                *reinterpret_cast<float2*>(C + (long long)m * N + col) = make_float2(v0, v1);
            }
        }
}

// ---------------------------------------------------------------------------
// pair8_k: relu(pair @ w01 + b01). 128x128x256, 256 threads, 8 warps 2m x 4n,
// warp tile 64x32 (MT=4, NT=4). Loader spread over all threads.
// ---------------------------------------------------------------------------
__global__ void __launch_bounds__(256)
pair8_k(const float* __restrict__ sub, const float* __restrict__ W,
        const float* __restrict__ bias, float* __restrict__ C)
{
    constexpr int BM = 128, BN = 128, MT = 4, NT = 4;
    constexpr int nk = C0 / 8;   // 32

    __shared__ __align__(16) float As[2][BM][12];
    __shared__ __align__(16) float Bs[2][BN][12];

    const int tid = threadIdx.x, lane = tid & 31, wid = tid >> 5;
    const int lr = lane >> 2, lc = lane & 3;
    const int wm = (wid & 1) * 64;
    const int wn = (wid >> 1) * 32;
    const int m0 = blockIdx.x * BM;

    const int arow = tid & 127;
    const int kq   = tid >> 7;          // 0/1: which half of the 8-k slab

    const int m  = m0 + arow;
    const int pb = m / NN;
    const int pr = m - pb * NN;
    const int pi = pr / NTOK;
    const int pj = pr - pi * NTOK;
    const float* rowI = sub + (long long)(pb * NTOK + pi) * C0;
    const float* rowJ = sub + (long long)(pb * NTOK + pj) * C0;

    const unsigned aB = (unsigned)__cvta_generic_to_shared(&As[0][0][0]);
    const unsigned bB = (unsigned)__cvta_generic_to_shared(&Bs[0][0][0]);
    const unsigned aOff = ((lane & 7) + ((lane & 8) ? 8 : 0)) * 48 + ((lane & 16) ? 16 : 0);
    const unsigned bOff = ((lane & 7) + ((lane & 16) ? 8 : 0)) * 48 + ((lane & 8) ? 16 : 0);

    float aReg[4], bReg[4];
    float acc[MT][NT][4];
    #pragma unroll
    for (int mt = 0; mt < MT; mt++)
        #pragma unroll
        for (int nt = 0; nt < NT; nt++)
            #pragma unroll
            for (int c = 0; c < 4; c++) acc[mt][nt][c] = 0.f;

    auto loadA = [&](int kt) {
        const int k = kt * 8 + kq * 4;
        const float4 a0 = *reinterpret_cast<const float4*>(rowI + k);
        const float4 b0 = *reinterpret_cast<const float4*>(rowJ + k);
        aReg[0] = a0.x * b0.x; aReg[1] = a0.y * b0.y;
        aReg[2] = a0.z * b0.z; aReg[3] = a0.w * b0.w;
    };
    auto loadB = [&](int kt) {
        const int k = kt * 8 + kq * 4;
        #pragma unroll
        for (int kk = 0; kk < 4; kk++) bReg[kk] = W[(k + kk) * C1 + arow];
    };
    auto stS = [&](int buf) {
        *reinterpret_cast<float4*>(&As[buf][arow][kq * 4]) =
            make_float4(tf32f(aReg[0]), tf32f(aReg[1]), tf32f(aReg[2]), tf32f(aReg[3]));
        *reinterpret_cast<float4*>(&Bs[buf][arow][kq * 4]) =
            make_float4(tf32f(bReg[0]), tf32f(bReg[1]), tf32f(bReg[2]), tf32f(bReg[3]));
    };

    loadA(0); loadB(0); stS(0);
    __syncthreads();

    for (int kt = 0; kt < nk; ++kt) {
        const int cur = kt & 1;
        if (kt + 1 < nk) { loadA(kt + 1); loadB(kt + 1); }
        const unsigned aAddr = aB + cur * (BM * 48) + wm * 48 + aOff;
        const unsigned bAddr = bB + cur * (BN * 48) + wn * 48 + bOff;
        unsigned af[MT][4], bf[NT][2];
        #pragma unroll
        for (int mt = 0; mt < MT; mt++)
            ldsm4(af[mt][0], af[mt][1], af[mt][2], af[mt][3], aAddr + mt * 768);
        #pragma unroll
        for (int g = 0; g < NT / 2; g++) {
            unsigned r0, r1, r2, r3;
            ldsm4(r0, r1, r2, r3, bAddr + g * 768);
            bf[2 * g][0] = r0; bf[2 * g][1] = r1;
            bf[2 * g + 1][0] = r2; bf[2 * g + 1][1] = r3;
        }
        #pragma unroll
        for (int mt = 0; mt < MT; mt++)
            #pragma unroll
            for (int nt = 0; nt < NT; nt++)
                mma_tf32(acc[mt][nt], af[mt], bf[nt]);
        if (kt + 1 < nk) stS(cur ^ 1);
        __syncthreads();
    }

    #pragma unroll
    for (int mt = 0; mt < MT; mt++)
        #pragma unroll
        for (int nt = 0; nt < NT; nt++) {
            const int col = wn + nt * 8 + 2 * lc;
            #pragma unroll
            for (int h = 0; h < 2; h++) {
                const long long row = m0 + wm + mt * 16 + lr + h * 8;
                float v0 = fmaxf(acc[mt][nt][2 * h]     + bias[col],     0.f);
                float v1 = fmaxf(acc[mt][nt][2 * h + 1] + bias[col + 1], 0.f);
                *reinterpret_cast<float2*>(C + row * C1 + col) = make_float2(v0, v1);
            }
        }
}

// ---------------------------------------------------------------------------
// conv1f16_k: factorized conv1 (256->128, dil 1). One block per (b,i),
// 512 threads, 16 warps 4m x 4n, warp tile 64x32 (MT=4, NT=4), K=768.
// H computed on the fly: 6 LDG + 6 FMA per thread per kt.
// ---------------------------------------------------------------------------
__global__ void __launch_bounds__(512)
conv1f16_k(const float* __restrict__ sub, const float* __restrict__ W,
           const float* __restrict__ bias, float* __restrict__ Out)
{
    constexpr int BM = 256, BN = 128, MT = 4, NT = 4;
    constexpr int nk = KH / 8;   // 96

    __shared__ __align__(16) float As[2][BM][12];
    __shared__ __align__(16) float Bs[2][BN][12];
    __shared__ float sR[KH];

    const int tid = threadIdx.x, lane = tid & 31, wid = tid >> 5;
    const int lr = lane >> 2, lc = lane & 3;
    const int wm = (wid & 3) * 64;
    const int wn = (wid >> 2) * 32;
    const int z  = blockIdx.x;          // b*196 + i
    const int b  = z / NTOK;
    const int i  = z - b * NTOK;
    const float* subB = sub + (long long)b * NTOK * C0;

    for (int idx = tid; idx < KH; idx += 512) {
        const int p = idx >> 8, c = idx & 255;
        const int ii = i + p - 1;
        sR[idx] = (ii >= 0 && ii < NTOK) ? subB[ii * C0 + c] : 0.f;
    }
    __syncthreads();

    const unsigned aB = (unsigned)__cvta_generic_to_shared(&As[0][0][0]);
    const unsigned bB = (unsigned)__cvta_generic_to_shared(&Bs[0][0][0]);
    const unsigned aOff = ((lane & 7) + ((lane & 8) ? 8 : 0)) * 48 + ((lane & 16) ? 16 : 0);
    const unsigned bOff = ((lane & 7) + ((lane & 16) ? 8 : 0)) * 48 + ((lane & 8) ? 16 : 0);

    const int arow = tid & 255;          // A row (j)
    const int akq  = tid >> 8;           // 0/1: k-half for A
    const int bd   = tid & 127;          // B col (d)
    const int bgrp = tid >> 7;           // 0..3: 2 k-rows each

    float aReg[4], bReg[2];
    float acc[MT][NT][4];
    #pragma unroll
    for (int mt = 0; mt < MT; mt++)
        #pragma unroll
        for (int nt = 0; nt < NT; nt++)
            #pragma unroll
            for (int c = 0; c < 4; c++) acc[mt][nt][c] = 0.f;

    auto loadA = [&](int kt) {
        const int k = kt * 8 + akq * 4;
        const int q = k >> 8;
        const int c = k & 255;
        const int jj = arow + q - 1;
        if (arow < NTOK && jj >= 0 && jj < NTOK) {
            const float4 v = *reinterpret_cast<const float4*>(subB + jj * C0 + c);
            aReg[0] = v.x; aReg[1] = v.y; aReg[2] = v.z; aReg[3] = v.w;
        } else {
            aReg[0] = aReg[1] = aReg[2] = aReg[3] = 0.f;
        }
    };
    auto loadB = [&](int kt) {
        #pragma unroll
        for (int kk = 0; kk < 2; kk++) {
            const int k = kt * 8 + bgrp * 2 + kk;
            const int q = k >> 8;
            const int c = k & 255;
            float h = sR[c] * W[((size_t)(q * C0 + c)) * C1 + bd];
            h = fmaf(sR[C0 + c],     W[((size_t)((3 + q) * C0 + c)) * C1 + bd], h);
            h = fmaf(sR[2 * C0 + c], W[((size_t)((6 + q) * C0 + c)) * C1 + bd], h);
            bReg[kk] = h;
        }
    };
    auto stS = [&](int buf) {
        *reinterpret_cast<float4*>(&As[buf][arow][akq * 4]) =
            make_float4(tf32f(aReg[0]), tf32f(aReg[1]), tf32f(aReg[2]), tf32f(aReg[3]));
        *reinterpret_cast<float2*>(&Bs[buf][bd][bgrp * 2]) =
            make_float2(tf32f(bReg[0]), tf32f(bReg[1]));
    };

    loadA(0); loadB(0); stS(0);
    __syncthreads();

    for (int kt = 0; kt < nk; ++kt) {
        const int cur = kt & 1;
        if (kt + 1 < nk) { loadA(kt + 1); loadB(kt + 1); }
        const unsigned aAddr = aB + cur * (BM * 48) + wm * 48 + aOff;
        const unsigned bAddr = bB + cur * (BN * 48) + wn * 48 + bOff;
        unsigned af[MT][4], bf[NT][2];
        #pragma unroll
        for (int mt = 0; mt < MT; mt++)
            ldsm4(af[mt][0], af[mt][1], af[mt][2], af[mt][3], aAddr + mt * 768);
        #pragma unroll
        for (int g = 0; g < NT / 2; g++) {
            unsigned r0, r1, r2, r3;
            ldsm4(r0, r1, r2, r3, bAddr + g * 768);
            bf[2 * g][0] = r0; bf[2 * g][1] = r1;
            bf[2 * g + 1][0] = r2; bf[2 * g + 1][1] = r3;
        }
        #pragma unroll
        for (int mt = 0; mt < MT; mt++)
            #pragma unroll
            for (int nt = 0; nt < NT; nt++)
                mma_tf32(acc[mt][nt], af[mt], bf[nt]);
        if (kt + 1 < nk) stS(cur ^ 1);
        __syncthreads();
    }

    #pragma unroll
    for (int mt = 0; mt < MT; mt++)
        #pragma unroll
        for (int nt = 0; nt < NT; nt++) {
            const int col = wn + nt * 8 + 2 * lc;
            #pragma unroll
            for (int h = 0; h < 2; h++) {
                const int j = wm + mt * 16 + lr + h * 8;
                if (j >= NTOK) continue;
                const long long mm = (long long)b * NN + (long long)i * NTOK + j;
                float v0 = fmaxf(acc[mt][nt][2 * h]     + bias[col],     0.f);
                float v1 = fmaxf(acc[mt][nt][2 * h + 1] + bias[col + 1], 0.f);
                *reinterpret_cast<float2*>(Out + mm * C1 + col) = make_float2(v0, v1);
            }
        }
}

// ---------------------------------------------------------------------------
// conv24b_k: conv2 (128->64, W-dil=2), single K=1152 implicit GEMM.
// 256 threads, 8 warps 2m x 4n over BN=64 (warp tile 64x16, MT=4, NT=2).
// ---------------------------------------------------------------------------
__global__ void __launch_bounds__(256)
conv24b_k(const float* __restrict__ In, const float* __restrict__ W,
          const float* __restrict__ bias, float* __restrict__ Out)
{
    constexpr int BM = 128, BN = 64, MT = 4, NT = 2;
    constexpr int nk = (9 * C1) / 8;   // 144

    __shared__ __align__(16) float As[2][BM][12];
    __shared__ __align__(16) float Bs[2][BN][12];
    __shared__ int rowbase[9][BM];

    const int tid = threadIdx.x, lane = tid & 31, wid = tid >> 5;
    const int lr = lane >> 2, lc = lane & 3;
    const int wm = (wid & 1) * 64;
    const int wn = (wid >> 1) * 16;
    const int m0 = blockIdx.x * BM;

    if (tid < BM) {
        const int m = m0 + tid;
        const int pb = m / NN;
        const int r = m - pb * NN;
        const int pi = r / NTOK;
        const int pj = r - pi * NTOK;
        #pragma unroll
        for (int tap = 0; tap < 9; tap++) {
            const int p = tap / 3 - 1, q = tap % 3 - 1;
            const int ii = pi + p, jj = pj + q * 2;
            rowbase[tap][tid] = (ii >= 0 && ii < NTOK && jj >= 0 && jj < NTOK)
                              ? ((pb * NTOK + ii) * NTOK + jj) * C1 : -1;
        }
    }
    __syncthreads();

    const unsigned aB = (unsigned)__cvta_generic_to_shared(&As[0][0][0]);
    const unsigned bB = (unsigned)__cvta_generic_to_shared(&Bs[0][0][0]);
    const unsigned aOff = ((lane & 7) + ((lane & 8) ? 8 : 0)) * 48 + ((lane & 16) ? 16 : 0);
    const unsigned bOff = ((lane & 7) + ((lane & 16) ? 8 : 0)) * 48 + ((lane & 8) ? 16 : 0);

    const int arow = tid & 127;
    const int akq  = tid >> 7;          // 0/1
    const int bd   = tid & 63;
    const int bgrp = tid >> 6;          // 0..3: 2 k-rows each

    float aReg[4], bReg[2];
    float acc[MT][NT][4];
    #pragma unroll
    for (int mt = 0; mt < MT; mt++)
        #pragma unroll
        for (int nt = 0; nt < NT; nt++)
            #pragma unroll
            for (int c = 0; c < 4; c++) acc[mt][nt][c] = 0.f;

    auto loadA = [&](int kt) {
        const int k = kt * 8 + akq * 4;
        const int tap = k >> 7;
        const int c = k & 127;
        const int base = rowbase[tap][arow];
        if (base >= 0) {
            const float4 v = *reinterpret_cast<const float4*>(In + base + c);
            aReg[0] = v.x; aReg[1] = v.y; aReg[2] = v.z; aReg[3] = v.w;
        } else {
            aReg[0] = aReg[1] = aReg[2] = aReg[3] = 0.f;
        }
    };
    auto loadB = [&](int kt) {
        #pragma unroll
        for (int kk = 0; kk < 2; kk++) {
            const int k = kt * 8 + bgrp * 2 + kk;
            const int tap = k >> 7;
            const int c = k & 127;
            bReg[kk] = W[((size_t)(tap * C1 + c)) * C2 + bd];
        }
    };
    auto stS = [&](int buf) {
        *reinterpret_cast<float4*>(&As[buf][arow][akq * 4]) =
            make_float4(tf32f(aReg[0]), tf32f(aReg[1]), tf32f(aReg[2]), tf32f(aReg[3]));
        *reinterpret_cast<float2*>(&Bs[buf][bd][bgrp * 2]) =
            make_float2(tf32f(bReg[0]), tf32f(bReg[1]));
    };

    loadA(0); loadB(0); stS(0);
    __syncthreads();

    for (int kt = 0; kt < nk; ++kt) {
        const int cur = kt & 1;
        if (kt + 1 < nk) { loadA(kt + 1); loadB(kt + 1); }
        const unsigned aAddr = aB + cur * (BM * 48) + wm * 48 + aOff;
        const unsigned bAddr = bB + cur * (BN * 48) + wn * 48 + bOff;
        unsigned af[MT][4], bf[NT][2];
        #pragma unroll
        for (int mt = 0; mt < MT; mt++)
            ldsm4(af[mt][0], af[mt][1], af[mt][2], af[mt][3], aAddr + mt * 768);
        {
            unsigned r0, r1, r2, r3;
            ldsm4(r0, r1, r2, r3, bAddr);
            bf[0][0] = r0; bf[0][1] = r1;
            bf[1][0] = r2; bf[1][1] = r3;
        }
        #pragma unroll
        for (int mt = 0; mt < MT; mt++)
            #pragma unroll
            for (int nt = 0; nt < NT; nt++)
                mma_tf32(acc[mt][nt], af[mt], bf[nt]);
        if (kt + 1 < nk) stS(cur ^ 1);
        __syncthreads();
    }

    #pragma unroll
    for (int mt = 0; mt < MT; mt++)
        #pragma unroll
        for (int nt = 0; nt < NT; nt++) {
            const int col = wn + nt * 8 + 2 * lc;
            #pragma unroll
            for (int h = 0; h < 2; h++) {
                const long long row = m0 + wm + mt * 16 + lr + h * 8;
                float v0 = fmaxf(acc[mt][nt][2 * h]     + bias[col],     0.f);
                float v1 = fmaxf(acc[mt][nt][2 * h + 1] + bias[col + 1], 0.f);
                *reinterpret_cast<float2*>(Out + row * C2 + col) = make_float2(v0, v1);
            }
        }
}

// ---------------------------------------------------------------------------
// gemm64L0_k: L0 = relu( relu(s1 @ w02 + b02) . w03 + b03 ). 8 warps 16x64.
// ---------------------------------------------------------------------------
__global__ void __launch_bounds__(256)
gemm64L0_k(const float* __restrict__ A, const float* __restrict__ B,
           const float* __restrict__ bias, const float* __restrict__ w03,
           const float* __restrict__ b03, float* __restrict__ L0)
{
    constexpr int BM = 128, BN = 64, BK = 8;
    constexpr int NT = 8;
    constexpr int AP = BM + 8, BP = BN + 8;
    constexpr int K = C1, N = C2;
    constexpr int nk = K / BK;  // 16

    const int tid  = threadIdx.x;
    const int wid  = tid >> 5, lane = tid & 31;
    const int lr   = lane >> 2, lc = lane & 3;
    const int wm   = wid * 16;
    const int m0   = blockIdx.x * BM;

    __shared__ __align__(16) float As[2][BK][AP];
    __shared__ __align__(16) float Bs[2][BK][BP];

    const int ar = tid >> 1;
    const int ak = (tid & 1) * 4;
    const int bk = tid >> 5;
    const int bc = (tid & 31) * 2;

    float aReg[4], bReg[2];
    float acc[NT][4];
    #pragma unroll
    for (int nt = 0; nt < NT; nt++)
        #pragma unroll
        for (int c = 0; c < 4; c++) acc[nt][c] = 0.f;

    auto loadA = [&](int kt) {
        const int k = kt * BK + ak;
        const float4 v = *reinterpret_cast<const float4*>(A + (long long)(m0 + ar) * K + k);
        aReg[0] = v.x; aReg[1] = v.y; aReg[2] = v.z; aReg[3] = v.w;
    };
    auto loadB = [&](int kt) {
        const int k = kt * BK + bk;
        const float2 v = *reinterpret_cast<const float2*>(B + (long long)k * N + bc);
        bReg[0] = v.x; bReg[1] = v.y;
    };
    auto stS = [&](int buf) {
        #pragma unroll
        for (int c = 0; c < 4; c++) As[buf][ak + c][ar] = tf32f(aReg[c]);
        #pragma unroll
        for (int c = 0; c < 2; c++) Bs[buf][bk][bc + c] = tf32f(bReg[c]);
    };

    loadA(0); loadB(0); stS(0);
    __syncthreads();

    for (int kt = 0; kt < nk; ++kt) {
        const int cur = kt & 1;
        if (kt + 1 < nk) { loadA(kt + 1); loadB(kt + 1); }
        unsigned af[4], bf[NT][2];
        {
            const int r = wm + lr;
            af[0] = fu(As[cur][lc    ][r]);
            af[1] = fu(As[cur][lc    ][r + 8]);
            af[2] = fu(As[cur][lc + 4][r]);
            af[3] = fu(As[cur][lc + 4][r + 8]);
        }
        #pragma unroll
        for (int nt = 0; nt < NT; nt++) {
            const int n = nt * 8 + lr;
            bf[nt][0] = fu(Bs[cur][lc    ][n]);
            bf[nt][1] = fu(Bs[cur][lc + 4][n]);
        }
        #pragma unroll
        for (int nt = 0; nt < NT; nt++)
            mma_tf32(acc[nt], af, bf[nt]);
        if (kt + 1 < nk) stS(cur ^ 1);
        __syncthreads();
    }

    float part0 = 0.f, part1 = 0.f;
    #pragma unroll
    for (int nt = 0; nt < NT; nt++) {
        const int col = nt * 8 + 2 * lc;
        const float w0 = w03[col], w1v = w03[col + 1];
        part0 += fmaxf(acc[nt][0] + bias[col], 0.f) * w0
               + fmaxf(acc[nt][1] + bias[col + 1], 0.f) * w1v;
        part1 += fmaxf(acc[nt][2] + bias[col], 0.f) * w0
               + fmaxf(acc[nt][3] + bias[col + 1], 0.f) * w1v;
    }
    part0 += __shfl_xor_sync(0xffffffffu, part0, 1);
    part0 += __shfl_xor_sync(0xffffffffu, part0, 2);
    part1 += __shfl_xor_sync(0xffffffffu, part1, 1);
    part1 += __shfl_xor_sync(0xffffffffu, part1, 2);
    if (lc == 0) {
        L0[m0 + wm + lr]     = fmaxf(part0 + b03[0], 0.f);
        L0[m0 + wm + lr + 8] = fmaxf(part1 + b03[0], 0.f);
    }
}

// ---------------------------------------------------------------------------
// Last conv (64 -> 1, dil 4): one warp per output pixel.
// ---------------------------------------------------------------------------
template<int CIN, int DILW>
__global__ void convlast_k(const float* __restrict__ In, const float* __restrict__ W,
                           const float* __restrict__ bias, float* __restrict__ Out)
{
    const int lane = threadIdx.x & 31;
    const int wp   = threadIdx.x >> 5;
    const int m    = blockIdx.x * 8 + wp;
    const int b = m / NN;
    const int r = m - b * NN;
    const int i = r / NTOK;
    const int j = r - i * NTOK;
    float acc = 0.f;
    #pragma unroll
    for (int tap = 0; tap < 9; ++tap) {
        const int p = tap / 3 - 1, q = tap % 3 - 1;
        const int ii = i + p, jj = j + q * DILW;
        if (ii >= 0 && ii < NTOK && jj >= 0 && jj < NTOK) {
            const float* src = In + (long long)((b * NTOK + ii) * NTOK + jj) * CIN;
            const float* w   = W + tap * CIN;
            acc = fmaf(src[lane],      w[lane],      acc);
            acc = fmaf(src[lane + 32], w[lane + 32], acc);
        }
    }
    #pragma unroll
    for (int off = 16; off; off >>= 1) acc += __shfl_xor_sync(0xffffffffu, acc, off);
    if (lane == 0) Out[m] = fmaxf(acc + bias[0], 0.f);
}

// softmax stats over symmetrized logits, per batch
__global__ void smax_stats_k()
{
    const int b = blockIdx.x;
    const float* Lb = (blockIdx.y ? g_L1 : g_L0) + b * NN;
    __shared__ float red[256];
    const int tid = threadIdx.x;
    float mx = -1e30f;
    for (int idx = tid; idx < NN; idx += 256) {
        const int i = idx / NTOK, j = idx - (idx / NTOK) * NTOK;
        mx = fmaxf(mx, Lb[idx] + Lb[j * NTOK + i]);
    }
    red[tid] = mx; __syncthreads();
    for (int s = 128; s; s >>= 1) {
        if (tid < s) red[tid] = fmaxf(red[tid], red[tid + s]);
        __syncthreads();
    }
    mx = red[0]; __syncthreads();
    float sum = 0.f;
    for (int idx = tid; idx < NN; idx += 256) {
        const int i = idx / NTOK, j = idx - (idx / NTOK) * NTOK;
        sum += expf(Lb[idx] + Lb[j * NTOK + i] - mx);
    }
    red[tid] = sum; __syncthreads();
    for (int s = 128; s; s >>= 1) {
        if (tid < s) red[tid] += red[tid + s];
        __syncthreads();
    }
    if (tid == 0) {
        g_stats[(blockIdx.y * 8 + b) * 2]     = mx;
        g_stats[(blockIdx.y * 8 + b) * 2 + 1] = red[0];
    }
}

// Mc = 0.5 * (softmax0 + softmax1)
__global__ void combine_k()
{
    const int idx = blockIdx.x * 256 + threadIdx.x;
    if (idx >= MTOT) return;
    const int b = idx / NN;
    const int r = idx - b * NN;
    const int i = r / NTOK;
    const int j = r - i * NTOK;
    const int t = b * NN + j * NTOK + i;
    const float s0 = g_L0[idx] + g_L0[t];
    const float s1 = g_L1[idx] + g_L1[t];
    const float m0 = g_stats[b * 2],      z0 = g_stats[b * 2 + 1];
    const float m1 = g_stats[16 + b * 2], z1 = g_stats[16 + b * 2 + 1];
    g_Mc[idx] = 0.5f * (expf(s0 - m0) / z0 + expf(s1 - m1) / z1);
}

// ---------------------------------------------------------------------------
extern "C" void kernel_launch(void* const* d_in, const int* in_sizes, int n_in,
                              void* d_out, int out_size)
{
    (void)in_sizes; (void)n_in; (void)out_size;
    const float* x     = (const float*)d_in[0];
    const float* w_prj = (const float*)d_in[1];
    const float* b_prj = (const float*)d_in[2];
    const float* w01   = (const float*)d_in[3];
    const float* b01   = (const float*)d_in[4];
    const float* w02   = (const float*)d_in[5];
    const float* b02   = (const float*)d_in[6];
    const float* w03   = (const float*)d_in[7];
    const float* b03   = (const float*)d_in[8];
    const float* w1    = (const float*)d_in[9];
    const float* b1    = (const float*)d_in[10];
    const float* w2    = (const float*)d_in[11];
    const float* b2    = (const float*)d_in[12];
    const float* w3    = (const float*)d_in[13];
    const float* b3    = (const float*)d_in[14];
    float* out = (float*)d_out;

    float *sub, *s1, *s2, *L0, *L1, *Mc;
    cudaGetSymbolAddress((void**)&sub,  g_sub);
    cudaGetSymbolAddress((void**)&s1,   g_s1);
    cudaGetSymbolAddress((void**)&s2,   g_s2);
    cudaGetSymbolAddress((void**)&L0,   g_L0);
    cudaGetSymbolAddress((void**)&L1,   g_L1);
    cudaGetSymbolAddress((void**)&Mc,   g_Mc);

    // 1. projection
    gemm_tc<false, true><<<dim3(13, 2, 1), 256>>>(
        x, w_prj, b_prj, sub, NBATCH * NTOK, INDIM, C0, 0, 0, 0);

    // 2. branch 0
    pair8_k<<<MTOT / 128, 256>>>(sub, w01, b01, s1);
    gemm64L0_k<<<MTOT / 128, 256>>>(s1, w02, b02, w03, b03, L0);

    // 3. branch 1
    conv1f16_k<<<NBATCH * NTOK, 512>>>(sub, w1, b1, s1);
    conv24b_k<<<MTOT / 128, 256>>>(s1, w2, b2, s2);
    convlast_k<64, 4><<<MTOT / 8, 256>>>(s2, w3, b3, L1);

    // 4. softmax + combine
    smax_stats_k<<<dim3(8, 2), 256>>>();
    combine_k<<<(MTOT + 255) / 256, 256>>>();

    // 5. aggregation
    gemm_tc<false, false><<<dim3(2, 16, 8), 256>>>(
        Mc, x, nullptr, out, NTOK, NTOK, INDIM,
        (long long)NN, (long long)NTOK * INDIM, (long long)NTOK * INDIM);
}

// round 13
// speedup vs baseline: 1.2517x; 1.2263x over previous
#include <cuda_runtime.h>
#include <math.h>

// ---------------------------------------------------------------------------
// Problem constants
// ---------------------------------------------------------------------------
namespace {
constexpr int NTOK   = 196;
constexpr int NBATCH = 8;
constexpr int NN     = NTOK * NTOK;        // 38416
constexpr int MTOT   = NBATCH * NN;        // 307328
constexpr int INDIM  = 2048;
constexpr int C0     = 256;
constexpr int C1     = 128;
constexpr int C2     = 64;
constexpr int KH     = 3 * C0;             // 768
constexpr int SROW   = 20;                 // smem row stride in floats (80B)
}

// ---------------------------------------------------------------------------
// tf32 mma / ldmatrix helpers
// ---------------------------------------------------------------------------
__device__ __forceinline__ unsigned cvt_tf32(float f) {
    unsigned r; asm("cvt.rna.tf32.f32 %0, %1;" : "=r"(r) : "f"(f)); return r;
}
__device__ __forceinline__ float tf32f(float f) {
    return __uint_as_float(cvt_tf32(f));
}
__device__ __forceinline__ void mma_tf32(float* d, const unsigned* a, const unsigned* b) {
    asm volatile(
        "mma.sync.aligned.m16n8k8.row.col.f32.tf32.tf32.f32 "
        "{%0,%1,%2,%3}, {%4,%5,%6,%7}, {%8,%9}, {%0,%1,%2,%3};"
        : "+f"(d[0]), "+f"(d[1]), "+f"(d[2]), "+f"(d[3])
        : "r"(a[0]), "r"(a[1]), "r"(a[2]), "r"(a[3]),
          "r"(b[0]), "r"(b[1]));
}
__device__ __forceinline__ unsigned fu(float f) { return __float_as_uint(f); }
__device__ __forceinline__ void ldsm4(unsigned& r0, unsigned& r1, unsigned& r2, unsigned& r3,
                                      unsigned addr) {
    asm volatile("ldmatrix.sync.aligned.m8n8.x4.shared.b16 {%0,%1,%2,%3}, [%4];"
                 : "=r"(r0), "=r"(r1), "=r"(r2), "=r"(r3) : "r"(addr));
}

// ---------------------------------------------------------------------------
// Scratch
// ---------------------------------------------------------------------------
__device__ float g_sub [NBATCH * NTOK * C0];
__device__ float g_s1  [(long long)MTOT * C1];
__device__ float g_s2  [(long long)MTOT * C2];
__device__ float g_H   [(long long)NBATCH * NTOK * KH * C1];   // 617 MB
__device__ float g_L0  [MTOT];
__device__ float g_L1  [MTOT];
__device__ float g_Mc  [MTOT];
__device__ float g_stats[32];

// ---------------------------------------------------------------------------
// Generic guarded tf32 TC GEMM (BN=128): projection + aggregation.
// ---------------------------------------------------------------------------
template<bool RELU, bool HASBIAS>
__global__ void __launch_bounds__(256)
gemm_tc(const float* __restrict__ A, const float* __restrict__ B,
        const float* __restrict__ bias, float* __restrict__ C,
        int M, int K, int N, long long sA, long long sB, long long sC)
{
    constexpr int BM = 128, BN = 128, BK = 8;
    constexpr int MT = 2, NT = 8;
    constexpr int AP = BM + 8, BP = BN + 8;

    A += (long long)blockIdx.z * sA;
    B += (long long)blockIdx.z * sB;
    C += (long long)blockIdx.z * sC;

    const int tid  = threadIdx.x;
    const int wid  = tid >> 5, lane = tid & 31;
    const int lr   = lane >> 2, lc = lane & 3;
    const int wm   = (wid % 4) * 32;
    const int wn   = (wid / 4) * 64;
    const int m0   = blockIdx.x * BM;
    const int n0   = blockIdx.y * BN;

    __shared__ __align__(16) float As[2][BK][AP];
    __shared__ __align__(16) float Bs[2][BK][BP];

    const int ar = tid >> 1;
    const int ak = (tid & 1) * 4;
    const int bk = tid >> 5;
    const int bc = (tid & 31) * 4;

    float aReg[4], bReg[4];
    float acc[MT][NT][4];
    #pragma unroll
    for (int mt = 0; mt < MT; mt++)
        #pragma unroll
        for (int nt = 0; nt < NT; nt++)
            #pragma unroll
            for (int c = 0; c < 4; c++) acc[mt][nt][c] = 0.f;

    const int nk = (K + BK - 1) / BK;

    auto loadA = [&](int kt) {
        const int m = m0 + ar;
        const int k = kt * BK + ak;
        if (m < M && (k + 3) < K) {
            const float4 v = *reinterpret_cast<const float4*>(A + (long long)m * K + k);
            aReg[0] = v.x; aReg[1] = v.y; aReg[2] = v.z; aReg[3] = v.w;
        } else {
            #pragma unroll
            for (int c = 0; c < 4; c++)
                aReg[c] = (m < M && (k + c) < K) ? A[(long long)m * K + k + c] : 0.f;
        }
    };
    auto loadB = [&](int kt) {
        const int k = kt * BK + bk;
        if (k < K) {
            const float4 v = *reinterpret_cast<const float4*>(B + (long long)k * N + n0 + bc);
            bReg[0] = v.x; bReg[1] = v.y; bReg[2] = v.z; bReg[3] = v.w;
        } else {
            #pragma unroll
            for (int c = 0; c < 4; c++) bReg[c] = 0.f;
        }
    };
    auto stS = [&](int buf) {
        #pragma unroll
        for (int c = 0; c < 4; c++) As[buf][ak + c][ar] = tf32f(aReg[c]);
        #pragma unroll
        for (int c = 0; c < 4; c++) Bs[buf][bk][bc + c] = tf32f(bReg[c]);
    };

    loadA(0); loadB(0); stS(0);
    __syncthreads();

    for (int kt = 0; kt < nk; ++kt) {
        const int cur = kt & 1;
        if (kt + 1 < nk) { loadA(kt + 1); loadB(kt + 1); }
        unsigned af[MT][4], bf[NT][2];
        #pragma unroll
        for (int mt = 0; mt < MT; mt++) {
            const int r = wm + mt * 16 + lr;
            af[mt][0] = fu(As[cur][lc    ][r]);
            af[mt][1] = fu(As[cur][lc    ][r + 8]);
            af[mt][2] = fu(As[cur][lc + 4][r]);
            af[mt][3] = fu(As[cur][lc + 4][r + 8]);
        }
        #pragma unroll
        for (int nt = 0; nt < NT; nt++) {
            const int n = wn + nt * 8 + lr;
            bf[nt][0] = fu(Bs[cur][lc    ][n]);
            bf[nt][1] = fu(Bs[cur][lc + 4][n]);
        }
        #pragma unroll
        for (int mt = 0; mt < MT; mt++)
            #pragma unroll
            for (int nt = 0; nt < NT; nt++)
                mma_tf32(acc[mt][nt], af[mt], bf[nt]);
        if (kt + 1 < nk) stS(cur ^ 1);
        __syncthreads();
    }

    #pragma unroll
    for (int mt = 0; mt < MT; mt++)
        #pragma unroll
        for (int nt = 0; nt < NT; nt++) {
            const int col = n0 + wn + nt * 8 + 2 * lc;
            #pragma unroll
            for (int h = 0; h < 2; h++) {
                const int m = m0 + wm + mt * 16 + lr + h * 8;
                if (m >= M) continue;
                float v0 = acc[mt][nt][2 * h];
                float v1 = acc[mt][nt][2 * h + 1];
                if constexpr (HASBIAS) { v0 += bias[col]; v1 += bias[col + 1]; }
                if constexpr (RELU)    { v0 = fmaxf(v0, 0.f); v1 = fmaxf(v1, 0.f); }
                *reinterpret_cast<float2*>(C + (long long)m * N + col) = make_float2(v0, v1);
            }
        }
}

// ---------------------------------------------------------------------------
// hbuild_k: H[z][(q,c)][d] = sum_p sub[b,i+p-1,c] * w1[p,q,c,d], tf32-rounded.
// float4 W loads + float4 coalesced stores; 4 z's per block amortize W reads.
// ---------------------------------------------------------------------------
__global__ void __launch_bounds__(256)
hbuild_k(const float* __restrict__ sub, const float* __restrict__ W,
         float* __restrict__ H)
{
    constexpr int ZPB = 4;
    __shared__ float sR[ZPB][KH];
    const int z0 = blockIdx.x * ZPB;
    const int tid = threadIdx.x;

    for (int idx = tid; idx < ZPB * KH; idx += 256) {
        const int zz = idx / KH;
        const int rem = idx - zz * KH;
        const int p = rem >> 8, c = rem & 255;
        const int z = z0 + zz;
        const int b = z / NTOK;
        const int i = z - b * NTOK;
        const int ii = i + p - 1;
        sR[zz][rem] = (ii >= 0 && ii < NTOK) ? sub[(b * NTOK + ii) * C0 + c] : 0.f;
    }
    __syncthreads();

    const int d4 = (tid & 31) * 4;
    const int rg = tid >> 5;                 // 0..7
    for (int r = rg; r < KH; r += 8) {
        const int q = r >> 8, c = r & 255;
        const float4 w0 = *reinterpret_cast<const float4*>(W + ((size_t)(q * C0 + c)) * C1 + d4);
        const float4 w1 = *reinterpret_cast<const float4*>(W + ((size_t)((3 + q) * C0 + c)) * C1 + d4);
        const float4 w2 = *reinterpret_cast<const float4*>(W + ((size_t)((6 + q) * C0 + c)) * C1 + d4);
        #pragma unroll
        for (int zz = 0; zz < ZPB; zz++) {
            const float s0 = sR[zz][c];
            const float s1 = sR[zz][C0 + c];
            const float s2 = sR[zz][2 * C0 + c];
            float4 h;
            h.x = tf32f(fmaf(s2, w2.x, fmaf(s1, w1.x, s0 * w0.x)));
            h.y = tf32f(fmaf(s2, w2.y, fmaf(s1, w1.y, s0 * w0.y)));
            h.z = tf32f(fmaf(s2, w2.z, fmaf(s1, w1.z, s0 * w0.z)));
            h.w = tf32f(fmaf(s2, w2.w, fmaf(s1, w1.w, s0 * w0.w)));
            *reinterpret_cast<float4*>(H + ((long long)(z0 + zz) * KH + r) * C1 + d4) = h;
        }
    }
}

// ---------------------------------------------------------------------------
// conv1g2_k: conv1 GEMM from precomputed H. BK=16, BM=128 (j tile), BN=128.
// grid (2 j-tiles, 1568 z). 256 threads, 8 warps 2m x 4n (warp 64x32), 2 blk/SM.
// ---------------------------------------------------------------------------
__global__ void __launch_bounds__(256, 2)
conv1g2_k(const float* __restrict__ sub, const float* __restrict__ H,
          const float* __restrict__ bias, float* __restrict__ Out)
{
    constexpr int BM = 128, BN = 128, MT = 4, NT = 4;
    constexpr int nk = KH / 16;   // 48

    __shared__ __align__(16) float As[2][BM][SROW];
    __shared__ __align__(16) float Bs[2][BN][SROW];

    const int tid = threadIdx.x, lane = tid & 31, wid = tid >> 5;
    const int lr = lane >> 2, lc = lane & 3;
    const int wm = (wid & 1) * 64;
    const int wn = (wid >> 1) * 32;
    const int j0 = blockIdx.x * BM;
    const int z  = blockIdx.y;
    const int b  = z / NTOK;
    const int i  = z - b * NTOK;
    const float* subB = sub + (long long)b * NTOK * C0;
    const float* Hz   = H + (long long)z * KH * C1;

    const unsigned aB = (unsigned)__cvta_generic_to_shared(&As[0][0][0]);
    const unsigned bB = (unsigned)__cvta_generic_to_shared(&Bs[0][0][0]);
    const unsigned aOff = ((lane & 7) + ((lane & 8) ? 8 : 0)) * (SROW * 4) + ((lane & 16) ? 16 : 0);
    const unsigned bOff = ((lane & 7) + ((lane & 16) ? 8 : 0)) * (SROW * 4) + ((lane & 8) ? 16 : 0);

    const int arow = tid & 127;
    const int ah   = tid >> 7;          // 0/1 -> k offset 0/8
    const int bd   = tid & 127;
    const int bh   = tid >> 7;

    float aReg[8], bReg[8];
    float acc[MT][NT][4];
    #pragma unroll
    for (int mt = 0; mt < MT; mt++)
        #pragma unroll
        for (int nt = 0; nt < NT; nt++)
            #pragma unroll
            for (int c = 0; c < 4; c++) acc[mt][nt][c] = 0.f;

    auto loadA = [&](int kt) {
        const int kg = kt * 16 + ah * 8;
        const int q = kg >> 8;
        const int c = kg & 255;
        const int j = j0 + arow;
        const int jj = j + q - 1;
        if (j < NTOK && jj >= 0 && jj < NTOK) {
            const float4 v0 = *reinterpret_cast<const float4*>(subB + jj * C0 + c);
            const float4 v1 = *reinterpret_cast<const float4*>(subB + jj * C0 + c + 4);
            aReg[0] = v0.x; aReg[1] = v0.y; aReg[2] = v0.z; aReg[3] = v0.w;
            aReg[4] = v1.x; aReg[5] = v1.y; aReg[6] = v1.z; aReg[7] = v1.w;
        } else {
            #pragma unroll
            for (int c2 = 0; c2 < 8; c2++) aReg[c2] = 0.f;
        }
    };
    auto loadB = [&](int kt) {
        const float* Hp = Hz + (long long)(kt * 16 + bh * 8) * C1 + bd;
        #pragma unroll
        for (int kk = 0; kk < 8; kk++) bReg[kk] = Hp[kk * C1];
    };
    auto stS = [&](int buf) {
        *reinterpret_cast<float4*>(&As[buf][arow][ah * 8]) =
            make_float4(tf32f(aReg[0]), tf32f(aReg[1]), tf32f(aReg[2]), tf32f(aReg[3]));
        *reinterpret_cast<float4*>(&As[buf][arow][ah * 8 + 4]) =
            make_float4(tf32f(aReg[4]), tf32f(aReg[5]), tf32f(aReg[6]), tf32f(aReg[7]));
        *reinterpret_cast<float4*>(&Bs[buf][bd][bh * 8]) =
            make_float4(bReg[0], bReg[1], bReg[2], bReg[3]);   // H already tf32
        *reinterpret_cast<float4*>(&Bs[buf][bd][bh * 8 + 4]) =
            make_float4(bReg[4], bReg[5], bReg[6], bReg[7]);
    };

    loadA(0); loadB(0); stS(0);
    __syncthreads();

    for (int kt = 0; kt < nk; ++kt) {
        const int cur = kt & 1;
        if (kt + 1 < nk) { loadA(kt + 1); loadB(kt + 1); }
        const unsigned aBase = aB + cur * (BM * SROW * 4) + wm * (SROW * 4) + aOff;
        const unsigned bBase = bB + cur * (BN * SROW * 4) + wn * (SROW * 4) + bOff;
        #pragma unroll
        for (int ks = 0; ks < 2; ks++) {
            unsigned af[MT][4], bf[NT][2];
            #pragma unroll
            for (int mt = 0; mt < MT; mt++)
                ldsm4(af[mt][0], af[mt][1], af[mt][2], af[mt][3],
                      aBase + mt * 16 * SROW * 4 + ks * 32);
            #pragma unroll
            for (int g = 0; g < NT / 2; g++) {
                unsigned r0, r1, r2, r3;
                ldsm4(r0, r1, r2, r3, bBase + g * 16 * SROW * 4 + ks * 32);
                bf[2 * g][0] = r0; bf[2 * g][1] = r1;
                bf[2 * g + 1][0] = r2; bf[2 * g + 1][1] = r3;
            }
            #pragma unroll
            for (int mt = 0; mt < MT; mt++)
                #pragma unroll
                for (int nt = 0; nt < NT; nt++)
                    mma_tf32(acc[mt][nt], af[mt], bf[nt]);
        }
        if (kt + 1 < nk) stS(cur ^ 1);
        __syncthreads();
    }

    #pragma unroll
    for (int mt = 0; mt < MT; mt++)
        #pragma unroll
        for (int nt = 0; nt < NT; nt++) {
            const int col = wn + nt * 8 + 2 * lc;
            #pragma unroll
            for (int h = 0; h < 2; h++) {
                const int j = j0 + wm + mt * 16 + lr + h * 8;
                if (j >= NTOK) continue;
                const long long mm = (long long)b * NN + (long long)i * NTOK + j;
                float v0 = fmaxf(acc[mt][nt][2 * h]     + bias[col],     0.f);
                float v1 = fmaxf(acc[mt][nt][2 * h + 1] + bias[col + 1], 0.f);
                *reinterpret_cast<float2*>(Out + mm * C1 + col) = make_float2(v0, v1);
            }
        }
}

// ---------------------------------------------------------------------------
// pair16_k: relu(pair @ w01 + b01). 128x128x256, BK=16, 8 warps 2m x 4n.
// ---------------------------------------------------------------------------
__global__ void __launch_bounds__(256, 2)
pair16_k(const float* __restrict__ sub, const float* __restrict__ W,
         const float* __restrict__ bias, float* __restrict__ C)
{
    constexpr int BM = 128, BN = 128, MT = 4, NT = 4;
    constexpr int nk = C0 / 16;   // 16

    __shared__ __align__(16) float As[2][BM][SROW];
    __shared__ __align__(16) float Bs[2][BN][SROW];

    const int tid = threadIdx.x, lane = tid & 31, wid = tid >> 5;
    const int lr = lane >> 2, lc = lane & 3;
    const int wm = (wid & 1) * 64;
    const int wn = (wid >> 1) * 32;
    const int m0 = blockIdx.x * BM;

    const int arow = tid & 127;
    const int ah   = tid >> 7;
    const int bd   = tid & 127;
    const int bh   = tid >> 7;

    const int m  = m0 + arow;
    const int pb = m / NN;
    const int pr = m - pb * NN;
    const int pi = pr / NTOK;
    const int pj = pr - pi * NTOK;
    const float* rowI = sub + (long long)(pb * NTOK + pi) * C0;
    const float* rowJ = sub + (long long)(pb * NTOK + pj) * C0;

    const unsigned aB = (unsigned)__cvta_generic_to_shared(&As[0][0][0]);
    const unsigned bB = (unsigned)__cvta_generic_to_shared(&Bs[0][0][0]);
    const unsigned aOff = ((lane & 7) + ((lane & 8) ? 8 : 0)) * (SROW * 4) + ((lane & 16) ? 16 : 0);
    const unsigned bOff = ((lane & 7) + ((lane & 16) ? 8 : 0)) * (SROW * 4) + ((lane & 8) ? 16 : 0);

    float aReg[8], bReg[8];
    float acc[MT][NT][4];
    #pragma unroll
    for (int mt = 0; mt < MT; mt++)
        #pragma unroll
        for (int nt = 0; nt < NT; nt++)
            #pragma unroll
            for (int c = 0; c < 4; c++) acc[mt][nt][c] = 0.f;

    auto loadA = [&](int kt) {
        const int k = kt * 16 + ah * 8;
        const float4 a0 = *reinterpret_cast<const float4*>(rowI + k);
        const float4 a1 = *reinterpret_cast<const float4*>(rowI + k + 4);
        const float4 b0 = *reinterpret_cast<const float4*>(rowJ + k);
        const float4 b1 = *reinterpret_cast<const float4*>(rowJ + k + 4);
        aReg[0] = a0.x * b0.x; aReg[1] = a0.y * b0.y; aReg[2] = a0.z * b0.z; aReg[3] = a0.w * b0.w;
        aReg[4] = a1.x * b1.x; aReg[5] = a1.y * b1.y; aReg[6] = a1.z * b1.z; aReg[7] = a1.w * b1.w;
    };
    auto loadB = [&](int kt) {
        const float* Wp = W + (kt * 16 + bh * 8) * C1 + bd;
        #pragma unroll
        for (int kk = 0; kk < 8; kk++) bReg[kk] = Wp[kk * C1];
    };
    auto stS = [&](int buf) {
        *reinterpret_cast<float4*>(&As[buf][arow][ah * 8]) =
            make_float4(tf32f(aReg[0]), tf32f(aReg[1]), tf32f(aReg[2]), tf32f(aReg[3]));
        *reinterpret_cast<float4*>(&As[buf][arow][ah * 8 + 4]) =
            make_float4(tf32f(aReg[4]), tf32f(aReg[5]), tf32f(aReg[6]), tf32f(aReg[7]));
        *reinterpret_cast<float4*>(&Bs[buf][bd][bh * 8]) =
            make_float4(tf32f(bReg[0]), tf32f(bReg[1]), tf32f(bReg[2]), tf32f(bReg[3]));
        *reinterpret_cast<float4*>(&Bs[buf][bd][bh * 8 + 4]) =
            make_float4(tf32f(bReg[4]), tf32f(bReg[5]), tf32f(bReg[6]), tf32f(bReg[7]));
    };

    loadA(0); loadB(0); stS(0);
    __syncthreads();

    for (int kt = 0; kt < nk; ++kt) {
        const int cur = kt & 1;
        if (kt + 1 < nk) { loadA(kt + 1); loadB(kt + 1); }
        const unsigned aBase = aB + cur * (BM * SROW * 4) + wm * (SROW * 4) + aOff;
        const unsigned bBase = bB + cur * (BN * SROW * 4) + wn * (SROW * 4) + bOff;
        #pragma unroll
        for (int ks = 0; ks < 2; ks++) {
            unsigned af[MT][4], bf[NT][2];
            #pragma unroll
            for (int mt = 0; mt < MT; mt++)
                ldsm4(af[mt][0], af[mt][1], af[mt][2], af[mt][3],
                      aBase + mt * 16 * SROW * 4 + ks * 32);
            #pragma unroll
            for (int g = 0; g < NT / 2; g++) {
                unsigned r0, r1, r2, r3;
                ldsm4(r0, r1, r2, r3, bBase + g * 16 * SROW * 4 + ks * 32);
                bf[2 * g][0] = r0; bf[2 * g][1] = r1;
                bf[2 * g + 1][0] = r2; bf[2 * g + 1][1] = r3;
            }
            #pragma unroll
            for (int mt = 0; mt < MT; mt++)
                #pragma unroll
                for (int nt = 0; nt < NT; nt++)
                    mma_tf32(acc[mt][nt], af[mt], bf[nt]);
        }
        if (kt + 1 < nk) stS(cur ^ 1);
        __syncthreads();
    }

    #pragma unroll
    for (int mt = 0; mt < MT; mt++)
        #pragma unroll
        for (int nt = 0; nt < NT; nt++) {
            const int col = wn + nt * 8 + 2 * lc;
            #pragma unroll
            for (int h = 0; h < 2; h++) {
                const long long row = m0 + wm + mt * 16 + lr + h * 8;
                float v0 = fmaxf(acc[mt][nt][2 * h]     + bias[col],     0.f);
                float v1 = fmaxf(acc[mt][nt][2 * h + 1] + bias[col + 1], 0.f);
                *reinterpret_cast<float2*>(C + row * C1 + col) = make_float2(v0, v1);
            }
        }
}

// ---------------------------------------------------------------------------
// conv24c_k: conv2 (128->64, W-dil=2) as single K=1152 implicit GEMM, BK=16.
// 8 warps 2m x 4n over BN=64 (warp tile 64x16, MT=4, NT=2).
// ---------------------------------------------------------------------------
__global__ void __launch_bounds__(256, 2)
conv24c_k(const float* __restrict__ In, const float* __restrict__ W,
          const float* __restrict__ bias, float* __restrict__ Out)
{
    constexpr int BM = 128, BN = 64, MT = 4, NT = 2;
    constexpr int nk = (9 * C1) / 16;   // 72

    __shared__ __align__(16) float As[2][BM][SROW];
    __shared__ __align__(16) float Bs[2][BN][SROW];
    __shared__ int rowbase[9][BM];

    const int tid = threadIdx.x, lane = tid & 31, wid = tid >> 5;
    const int lr = lane >> 2, lc = lane & 3;
    const int wm = (wid & 1) * 64;
    const int wn = (wid >> 1) * 16;
    const int m0 = blockIdx.x * BM;

    if (tid < BM) {
        const int m = m0 + tid;
        const int pb = m / NN;
        const int r = m - pb * NN;
        const int pi = r / NTOK;
        const int pj = r - pi * NTOK;
        #pragma unroll
        for (int tap = 0; tap < 9; tap++) {
            const int p = tap / 3 - 1, q = tap % 3 - 1;
            const int ii = pi + p, jj = pj + q * 2;
            rowbase[tap][tid] = (ii >= 0 && ii < NTOK && jj >= 0 && jj < NTOK)
                              ? ((pb * NTOK + ii) * NTOK + jj) * C1 : -1;
        }
    }
    __syncthreads();

    const unsigned aB = (unsigned)__cvta_generic_to_shared(&As[0][0][0]);
    const unsigned bB = (unsigned)__cvta_generic_to_shared(&Bs[0][0][0]);
    const unsigned aOff = ((lane & 7) + ((lane & 8) ? 8 : 0)) * (SROW * 4) + ((lane & 16) ? 16 : 0);
    const unsigned bOff = ((lane & 7) + ((lane & 16) ? 8 : 0)) * (SROW * 4) + ((lane & 8) ? 16 : 0);

    const int arow = tid & 127;
    const int ah   = tid >> 7;          // 0/1
    const int bd   = tid & 63;
    const int bg   = tid >> 6;          // 0..3 -> 4 k each

    float aReg[8], bReg[4];
    float acc[MT][NT][4];
    #pragma unroll
    for (int mt = 0; mt < MT; mt++)
        #pragma unroll
        for (int nt = 0; nt < NT; nt++)
            #pragma unroll
            for (int c = 0; c < 4; c++) acc[mt][nt][c] = 0.f;

    auto loadA = [&](int kt) {
        const int kg = kt * 16 + ah * 8;
        const int tap = kg >> 7;
        const int c = kg & 127;
        const int base = rowbase[tap][arow];
        if (base >= 0) {
            const float4 v0 = *reinterpret_cast<const float4*>(In + base + c);
            const float4 v1 = *reinterpret_cast<const float4*>(In + base + c + 4);
            aReg[0] = v0.x; aReg[1] = v0.y; aReg[2] = v0.z; aReg[3] = v0.w;
            aReg[4] = v1.x; aReg[5] = v1.y; aReg[6] = v1.z; aReg[7] = v1.w;
        } else {
            #pragma unroll
            for (int c2 = 0; c2 < 8; c2++) aReg[c2] = 0.f;
        }
    };
    auto loadB = [&](int kt) {
        #pragma unroll
        for (int kk = 0; kk < 4; kk++) {
            const int kg = kt * 16 + bg * 4 + kk;
            const int tap = kg >> 7;
            const int c = kg & 127;
            bReg[kk] = W[((size_t)(tap * C1 + c)) * C2 + bd];
        }
    };
    auto stS = [&](int buf) {
        *reinterpret_cast<float4*>(&As[buf][arow][ah * 8]) =
            make_float4(tf32f(aReg[0]), tf32f(aReg[1]), tf32f(aReg[2]), tf32f(aReg[3]));
        *reinterpret_cast<float4*>(&As[buf][arow][ah * 8 + 4]) =
            make_float4(tf32f(aReg[4]), tf32f(aReg[5]), tf32f(aReg[6]), tf32f(aReg[7]));
        *reinterpret_cast<float4*>(&Bs[buf][bd][bg * 4]) =
            make_float4(tf32f(bReg[0]), tf32f(bReg[1]), tf32f(bReg[2]), tf32f(bReg[3]));
    };

    loadA(0); loadB(0); stS(0);
    __syncthreads();

    for (int kt = 0; kt < nk; ++kt) {
        const int cur = kt & 1;
        if (kt + 1 < nk) { loadA(kt + 1); loadB(kt + 1); }
        const unsigned aBase = aB + cur * (BM * SROW * 4) + wm * (SROW * 4) + aOff;
        const unsigned bBase = bB + cur * (BN * SROW * 4) + wn * (SROW * 4) + bOff;
        #pragma unroll
        for (int ks = 0; ks < 2; ks++) {
            unsigned af[MT][4], bf[NT][2];
            #pragma unroll
            for (int mt = 0; mt < MT; mt++)
                ldsm4(af[mt][0], af[mt][1], af[mt][2], af[mt][3],
                      aBase + mt * 16 * SROW * 4 + ks * 32);
            {
                unsigned r0, r1, r2, r3;
                ldsm4(r0, r1, r2, r3, bBase + ks * 32);
                bf[0][0] = r0; bf[0][1] = r1;
                bf[1][0] = r2; bf[1][1] = r3;
            }
            #pragma unroll
            for (int mt = 0; mt < MT; mt++)
                #pragma unroll
                for (int nt = 0; nt < NT; nt++)
                    mma_tf32(acc[mt][nt], af[mt], bf[nt]);
        }
        if (kt + 1 < nk) stS(cur ^ 1);
        __syncthreads();
    }

    #pragma unroll
    for (int mt = 0; mt < MT; mt++)
        #pragma unroll
        for (int nt = 0; nt < NT; nt++) {
            const int col = wn + nt * 8 + 2 * lc;
            #pragma unroll
            for (int h = 0; h < 2; h++) {
                const long long row = m0 + wm + mt * 16 + lr + h * 8;
                float v0 = fmaxf(acc[mt][nt][2 * h]     + bias[col],     0.f);
                float v1 = fmaxf(acc[mt][nt][2 * h + 1] + bias[col + 1], 0.f);
                *reinterpret_cast<float2*>(Out + row * C2 + col) = make_float2(v0, v1);
            }
        }
}

// ---------------------------------------------------------------------------
// gemm64L0_k: L0 = relu( relu(s1 @ w02 + b02) . w03 + b03 ). 8 warps 16x64.
// ---------------------------------------------------------------------------
__global__ void __launch_bounds__(256)
gemm64L0_k(const float* __restrict__ A, const float* __restrict__ B,
           const float* __restrict__ bias, const float* __restrict__ w03,
           const float* __restrict__ b03, float* __restrict__ L0)
{
    constexpr int BM = 128, BN = 64, BK = 8;
    constexpr int NT = 8;
    constexpr int AP = BM + 8, BP = BN + 8;
    constexpr int K = C1, N = C2;
    constexpr int nk = K / BK;  // 16

    const int tid  = threadIdx.x;
    const int wid  = tid >> 5, lane = tid & 31;
    const int lr   = lane >> 2, lc = lane & 3;
    const int wm   = wid * 16;
    const int m0   = blockIdx.x * BM;

    __shared__ __align__(16) float As[2][BK][AP];
    __shared__ __align__(16) float Bs[2][BK][BP];

    const int ar = tid >> 1;
    const int ak = (tid & 1) * 4;
    const int bk = tid >> 5;
    const int bc = (tid & 31) * 2;

    float aReg[4], bReg[2];
    float acc[NT][4];
    #pragma unroll
    for (int nt = 0; nt < NT; nt++)
        #pragma unroll
        for (int c = 0; c < 4; c++) acc[nt][c] = 0.f;

    auto loadA = [&](int kt) {
        const int k = kt * BK + ak;
        const float4 v = *reinterpret_cast<const float4*>(A + (long long)(m0 + ar) * K + k);
        aReg[0] = v.x; aReg[1] = v.y; aReg[2] = v.z; aReg[3] = v.w;
    };
    auto loadB = [&](int kt) {
        const int k = kt * BK + bk;
        const float2 v = *reinterpret_cast<const float2*>(B + (long long)k * N + bc);
        bReg[0] = v.x; bReg[1] = v.y;
    };
    auto stS = [&](int buf) {
        #pragma unroll
        for (int c = 0; c < 4; c++) As[buf][ak + c][ar] = tf32f(aReg[c]);
        #pragma unroll
        for (int c = 0; c < 2; c++) Bs[buf][bk][bc + c] = tf32f(bReg[c]);
    };

    loadA(0); loadB(0); stS(0);
    __syncthreads();

    for (int kt = 0; kt < nk; ++kt) {
        const int cur = kt & 1;
        if (kt + 1 < nk) { loadA(kt + 1); loadB(kt + 1); }
        unsigned af[4], bf[NT][2];
        {
            const int r = wm + lr;
            af[0] = fu(As[cur][lc    ][r]);
            af[1] = fu(As[cur][lc    ][r + 8]);
            af[2] = fu(As[cur][lc + 4][r]);
            af[3] = fu(As[cur][lc + 4][r + 8]);
        }
        #pragma unroll
        for (int nt = 0; nt < NT; nt++) {
            const int n = nt * 8 + lr;
            bf[nt][0] = fu(Bs[cur][lc    ][n]);
            bf[nt][1] = fu(Bs[cur][lc + 4][n]);
        }
        #pragma unroll
        for (int nt = 0; nt < NT; nt++)
            mma_tf32(acc[nt], af, bf[nt]);
        if (kt + 1 < nk) stS(cur ^ 1);
        __syncthreads();
    }

    float part0 = 0.f, part1 = 0.f;
    #pragma unroll
    for (int nt = 0; nt < NT; nt++) {
        const int col = nt * 8 + 2 * lc;
        const float w0 = w03[col], w1v = w03[col + 1];
        part0 += fmaxf(acc[nt][0] + bias[col], 0.f) * w0
               + fmaxf(acc[nt][1] + bias[col + 1], 0.f) * w1v;
        part1 += fmaxf(acc[nt][2] + bias[col], 0.f) * w0
               + fmaxf(acc[nt][3] + bias[col + 1], 0.f) * w1v;
    }
    part0 += __shfl_xor_sync(0xffffffffu, part0, 1);
    part0 += __shfl_xor_sync(0xffffffffu, part0, 2);
    part1 += __shfl_xor_sync(0xffffffffu, part1, 1);
    part1 += __shfl_xor_sync(0xffffffffu, part1, 2);
    if (lc == 0) {
        L0[m0 + wm + lr]     = fmaxf(part0 + b03[0], 0.f);
        L0[m0 + wm + lr + 8] = fmaxf(part1 + b03[0], 0.f);
    }
}

// ---------------------------------------------------------------------------
// Last conv (64 -> 1, dil 4): one warp per output pixel.
// ---------------------------------------------------------------------------
template<int CIN, int DILW>
__global__ void convlast_k(const float* __restrict__ In, const float* __restrict__ W,
                           const float* __restrict__ bias, float* __restrict__ Out)
{
    const int lane = threadIdx.x & 31;
    const int wp   = threadIdx.x >> 5;
    const int m    = blockIdx.x * 8 + wp;
    const int b = m / NN;
    const int r = m - b * NN;
    const int i = r / NTOK;
    const int j = r - i * NTOK;
    float acc = 0.f;
    #pragma unroll
    for (int tap = 0; tap < 9; ++tap) {
        const int p = tap / 3 - 1, q = tap % 3 - 1;
        const int ii = i + p, jj = j + q * DILW;
        if (ii >= 0 && ii < NTOK && jj >= 0 && jj < NTOK) {
            const float* src = In + (long long)((b * NTOK + ii) * NTOK + jj) * CIN;
            const float* w   = W + tap * CIN;
            acc = fmaf(src[lane],      w[lane],      acc);
            acc = fmaf(src[lane + 32], w[lane + 32], acc);
        }
    }
    #pragma unroll
    for (int off = 16; off; off >>= 1) acc += __shfl_xor_sync(0xffffffffu, acc, off);
    if (lane == 0) Out[m] = fmaxf(acc + bias[0], 0.f);
}

// softmax stats over symmetrized logits, per batch
__global__ void smax_stats_k()
{
    const int b = blockIdx.x;
    const float* Lb = (blockIdx.y ? g_L1 : g_L0) + b * NN;
    __shared__ float red[256];
    const int tid = threadIdx.x;
    float mx = -1e30f;
    for (int idx = tid; idx < NN; idx += 256) {
        const int i = idx / NTOK, j = idx - (idx / NTOK) * NTOK;
        mx = fmaxf(mx, Lb[idx] + Lb[j * NTOK + i]);
    }
    red[tid] = mx; __syncthreads();
    for (int s = 128; s; s >>= 1) {
        if (tid < s) red[tid] = fmaxf(red[tid], red[tid + s]);
        __syncthreads();
    }
    mx = red[0]; __syncthreads();
    float sum = 0.f;
    for (int idx = tid; idx < NN; idx += 256) {
        const int i = idx / NTOK, j = idx - (idx / NTOK) * NTOK;
        sum += expf(Lb[idx] + Lb[j * NTOK + i] - mx);
    }
    red[tid] = sum; __syncthreads();
    for (int s = 128; s; s >>= 1) {
        if (tid < s) red[tid] += red[tid + s];
        __syncthreads();
    }
    if (tid == 0) {
        g_stats[(blockIdx.y * 8 + b) * 2]     = mx;
        g_stats[(blockIdx.y * 8 + b) * 2 + 1] = red[0];
    }
}

// Mc = 0.5 * (softmax0 + softmax1)
__global__ void combine_k()
{
    const int idx = blockIdx.x * 256 + threadIdx.x;
    if (idx >= MTOT) return;
    const int b = idx / NN;
    const int r = idx - b * NN;
    const int i = r / NTOK;
    const int j = r - i * NTOK;
    const int t = b * NN + j * NTOK + i;
    const float s0 = g_L0[idx] + g_L0[t];
    const float s1 = g_L1[idx] + g_L1[t];
    const float m0 = g_stats[b * 2],      z0 = g_stats[b * 2 + 1];
    const float m1 = g_stats[16 + b * 2], z1 = g_stats[16 + b * 2 + 1];
    g_Mc[idx] = 0.5f * (expf(s0 - m0) / z0 + expf(s1 - m1) / z1);
}

// ---------------------------------------------------------------------------
extern "C" void kernel_launch(void* const* d_in, const int* in_sizes, int n_in,
                              void* d_out, int out_size)
{
    (void)in_sizes; (void)n_in; (void)out_size;
    const float* x     = (const float*)d_in[0];
    const float* w_prj = (const float*)d_in[1];
    const float* b_prj = (const float*)d_in[2];
    const float* w01   = (const float*)d_in[3];
    const float* b01   = (const float*)d_in[4];
    const float* w02   = (const float*)d_in[5];
    const float* b02   = (const float*)d_in[6];
    const float* w03   = (const float*)d_in[7];
    const float* b03   = (const float*)d_in[8];
    const float* w1    = (const float*)d_in[9];
    const float* b1    = (const float*)d_in[10];
    const float* w2    = (const float*)d_in[11];
    const float* b2    = (const float*)d_in[12];
    const float* w3    = (const float*)d_in[13];
    const float* b3    = (const float*)d_in[14];
    float* out = (float*)d_out;

    float *sub, *s1, *s2, *H, *L0, *L1, *Mc;
    cudaGetSymbolAddress((void**)&sub,  g_sub);
    cudaGetSymbolAddress((void**)&s1,   g_s1);
    cudaGetSymbolAddress((void**)&s2,   g_s2);
    cudaGetSymbolAddress((void**)&H,    g_H);
    cudaGetSymbolAddress((void**)&L0,   g_L0);
    cudaGetSymbolAddress((void**)&L1,   g_L1);
    cudaGetSymbolAddress((void**)&Mc,   g_Mc);

    // 1. projection
    gemm_tc<false, true><<<dim3(13, 2, 1), 256>>>(
        x, w_prj, b_prj, sub, NBATCH * NTOK, INDIM, C0, 0, 0, 0);

    // 2. H factor build (independent of branch 0)
    hbuild_k<<<NBATCH * NTOK / 4, 256>>>(sub, w1, H);

    // 3. branch 0 (uses s1 first, then frees it for conv1)
    pair16_k<<<MTOT / 128, 256>>>(sub, w01, b01, s1);
    gemm64L0_k<<<MTOT / 128, 256>>>(s1, w02, b02, w03, b03, L0);

    // 4. branch 1
    conv1g2_k<<<dim3(2, NBATCH * NTOK), 256>>>(sub, H, b1, s1);
    conv24c_k<<<MTOT / 128, 256>>>(s1, w2, b2, s2);
    convlast_k<64, 4><<<MTOT / 8, 256>>>(s2, w3, b3, L1);

    // 5. softmax + combine
    smax_stats_k<<<dim3(8, 2), 256>>>();
    combine_k<<<(MTOT + 255) / 256, 256>>>();

    // 6. aggregation
    gemm_tc<false, false><<<dim3(2, 16, 8), 256>>>(
        Mc, x, nullptr, out, NTOK, NTOK, INDIM,
        (long long)NN, (long long)NTOK * INDIM, (long long)NTOK * INDIM);
}

// round 14
// speedup vs baseline: 1.2657x; 1.0112x over previous
#include <cuda_runtime.h>
#include <math.h>

// ---------------------------------------------------------------------------
// Problem constants
// ---------------------------------------------------------------------------
namespace {
constexpr int NTOK   = 196;
constexpr int NBATCH = 8;
constexpr int NN     = NTOK * NTOK;        // 38416
constexpr int MTOT   = NBATCH * NN;        // 307328
constexpr int INDIM  = 2048;
constexpr int C0     = 256;
constexpr int C1     = 128;
constexpr int C2     = 64;
constexpr int KH     = 3 * C0;             // 768
constexpr int SROW   = 20;                 // smem row stride in floats (80B)
// branch0_k dynamic smem layout (floats):
//   stage1: As [2][128][20] at 0 (5120), Bs at 5120 (5120)   -> 40 KB
//   stage2: s1s [128][132]  at 0 (16896), w02s [64][132] at 16896 (8448)
constexpr int B0_W02_OFF = 16896;
constexpr int B0_SMEM_FLOATS = 25344;      // 101376 bytes
}

// ---------------------------------------------------------------------------
// tf32 mma / ldmatrix helpers
// ---------------------------------------------------------------------------
__device__ __forceinline__ unsigned cvt_tf32(float f) {
    unsigned r; asm("cvt.rna.tf32.f32 %0, %1;" : "=r"(r) : "f"(f)); return r;
}
__device__ __forceinline__ float tf32f(float f) {
    return __uint_as_float(cvt_tf32(f));
}
__device__ __forceinline__ void mma_tf32(float* d, const unsigned* a, const unsigned* b) {
    asm volatile(
        "mma.sync.aligned.m16n8k8.row.col.f32.tf32.tf32.f32 "
        "{%0,%1,%2,%3}, {%4,%5,%6,%7}, {%8,%9}, {%0,%1,%2,%3};"
        : "+f"(d[0]), "+f"(d[1]), "+f"(d[2]), "+f"(d[3])
        : "r"(a[0]), "r"(a[1]), "r"(a[2]), "r"(a[3]),
          "r"(b[0]), "r"(b[1]));
}
__device__ __forceinline__ unsigned fu(float f) { return __float_as_uint(f); }
__device__ __forceinline__ void ldsm4(unsigned& r0, unsigned& r1, unsigned& r2, unsigned& r3,
                                      unsigned addr) {
    asm volatile("ldmatrix.sync.aligned.m8n8.x4.shared.b16 {%0,%1,%2,%3}, [%4];"
                 : "=r"(r0), "=r"(r1), "=r"(r2), "=r"(r3) : "r"(addr));
}

// ---------------------------------------------------------------------------
// Scratch
// ---------------------------------------------------------------------------
__device__ float g_sub [NBATCH * NTOK * C0];
__device__ float g_s1  [(long long)MTOT * C1];
__device__ float g_s2  [(long long)MTOT * C2];
__device__ float g_H   [(long long)NBATCH * NTOK * KH * C1];   // 617 MB
__device__ float g_L0  [MTOT];
__device__ float g_L1  [MTOT];
__device__ float g_Mc  [MTOT];
__device__ float g_stats[32];

// ---------------------------------------------------------------------------
// Generic guarded tf32 TC GEMM (BN=128): projection + aggregation.
// ---------------------------------------------------------------------------
template<bool RELU, bool HASBIAS>
__global__ void __launch_bounds__(256)
gemm_tc(const float* __restrict__ A, const float* __restrict__ B,
        const float* __restrict__ bias, float* __restrict__ C,
        int M, int K, int N, long long sA, long long sB, long long sC)
{
    constexpr int BM = 128, BN = 128, BK = 8;
    constexpr int MT = 2, NT = 8;
    constexpr int AP = BM + 8, BP = BN + 8;

    A += (long long)blockIdx.z * sA;
    B += (long long)blockIdx.z * sB;
    C += (long long)blockIdx.z * sC;

    const int tid  = threadIdx.x;
    const int wid  = tid >> 5, lane = tid & 31;
    const int lr   = lane >> 2, lc = lane & 3;
    const int wm   = (wid % 4) * 32;
    const int wn   = (wid / 4) * 64;
    const int m0   = blockIdx.x * BM;
    const int n0   = blockIdx.y * BN;

    __shared__ __align__(16) float As[2][BK][AP];
    __shared__ __align__(16) float Bs[2][BK][BP];

    const int ar = tid >> 1;
    const int ak = (tid & 1) * 4;
    const int bk = tid >> 5;
    const int bc = (tid & 31) * 4;

    float aReg[4], bReg[4];
    float acc[MT][NT][4];
    #pragma unroll
    for (int mt = 0; mt < MT; mt++)
        #pragma unroll
        for (int nt = 0; nt < NT; nt++)
            #pragma unroll
            for (int c = 0; c < 4; c++) acc[mt][nt][c] = 0.f;

    const int nk = (K + BK - 1) / BK;

    auto loadA = [&](int kt) {
        const int m = m0 + ar;
        const int k = kt * BK + ak;
        if (m < M && (k + 3) < K) {
            const float4 v = *reinterpret_cast<const float4*>(A + (long long)m * K + k);
            aReg[0] = v.x; aReg[1] = v.y; aReg[2] = v.z; aReg[3] = v.w;
        } else {
            #pragma unroll
            for (int c = 0; c < 4; c++)
                aReg[c] = (m < M && (k + c) < K) ? A[(long long)m * K + k + c] : 0.f;
        }
    };
    auto loadB = [&](int kt) {
        const int k = kt * BK + bk;
        if (k < K) {
            const float4 v = *reinterpret_cast<const float4*>(B + (long long)k * N + n0 + bc);
            bReg[0] = v.x; bReg[1] = v.y; bReg[2] = v.z; bReg[3] = v.w;
        } else {
            #pragma unroll
            for (int c = 0; c < 4; c++) bReg[c] = 0.f;
        }
    };
    auto stS = [&](int buf) {
        #pragma unroll
        for (int c = 0; c < 4; c++) As[buf][ak + c][ar] = tf32f(aReg[c]);
        #pragma unroll
        for (int c = 0; c < 4; c++) Bs[buf][bk][bc + c] = tf32f(bReg[c]);
    };

    loadA(0); loadB(0); stS(0);
    __syncthreads();

    for (int kt = 0; kt < nk; ++kt) {
        const int cur = kt & 1;
        if (kt + 1 < nk) { loadA(kt + 1); loadB(kt + 1); }
        unsigned af[MT][4], bf[NT][2];
        #pragma unroll
        for (int mt = 0; mt < MT; mt++) {
            const int r = wm + mt * 16 + lr;
            af[mt][0] = fu(As[cur][lc    ][r]);
            af[mt][1] = fu(As[cur][lc    ][r + 8]);
            af[mt][2] = fu(As[cur][lc + 4][r]);
            af[mt][3] = fu(As[cur][lc + 4][r + 8]);
        }
        #pragma unroll
        for (int nt = 0; nt < NT; nt++) {
            const int n = wn + nt * 8 + lr;
            bf[nt][0] = fu(Bs[cur][lc    ][n]);
            bf[nt][1] = fu(Bs[cur][lc + 4][n]);
        }
        #pragma unroll
        for (int mt = 0; mt < MT; mt++)
            #pragma unroll
            for (int nt = 0; nt < NT; nt++)
                mma_tf32(acc[mt][nt], af[mt], bf[nt]);
        if (kt + 1 < nk) stS(cur ^ 1);
        __syncthreads();
    }

    #pragma unroll
    for (int mt = 0; mt < MT; mt++)
        #pragma unroll
        for (int nt = 0; nt < NT; nt++) {
            const int col = n0 + wn + nt * 8 + 2 * lc;
            #pragma unroll
            for (int h = 0; h < 2; h++) {
                const int m = m0 + wm + mt * 16 + lr + h * 8;
                if (m >= M) continue;
                float v0 = acc[mt][nt][2 * h];
                float v1 = acc[mt][nt][2 * h + 1];
                if constexpr (HASBIAS) { v0 += bias[col]; v1 += bias[col + 1]; }
                if constexpr (RELU)    { v0 = fmaxf(v0, 0.f); v1 = fmaxf(v1, 0.f); }
                *reinterpret_cast<float2*>(C + (long long)m * N + col) = make_float2(v0, v1);
            }
        }
}

// ---------------------------------------------------------------------------
// hbuild_k: H[z][(q,c)][d] = sum_p sub[b,i+p-1,c] * w1[p,q,c,d], tf32-rounded.
// 8 z's per block amortize W reads; float4 loads + coalesced float4 stores.
// ---------------------------------------------------------------------------
__global__ void __launch_bounds__(256)
hbuild_k(const float* __restrict__ sub, const float* __restrict__ W,
         float* __restrict__ H)
{
    constexpr int ZPB = 8;
    __shared__ float sR[ZPB][KH];
    const int z0 = blockIdx.x * ZPB;
    const int tid = threadIdx.x;

    for (int idx = tid; idx < ZPB * KH; idx += 256) {
        const int zz = idx / KH;
        const int rem = idx - zz * KH;
        const int p = rem >> 8, c = rem & 255;
        const int z = z0 + zz;
        const int b = z / NTOK;
        const int i = z - b * NTOK;
        const int ii = i + p - 1;
        sR[zz][rem] = (ii >= 0 && ii < NTOK) ? sub[(b * NTOK + ii) * C0 + c] : 0.f;
    }
    __syncthreads();

    const int d4 = (tid & 31) * 4;
    const int rg = tid >> 5;                 // 0..7
    for (int r = rg; r < KH; r += 8) {
        const int q = r >> 8, c = r & 255;
        const float4 w0 = *reinterpret_cast<const float4*>(W + ((size_t)(q * C0 + c)) * C1 + d4);
        const float4 w1 = *reinterpret_cast<const float4*>(W + ((size_t)((3 + q) * C0 + c)) * C1 + d4);
        const float4 w2 = *reinterpret_cast<const float4*>(W + ((size_t)((6 + q) * C0 + c)) * C1 + d4);
        #pragma unroll
        for (int zz = 0; zz < ZPB; zz++) {
            const float s0 = sR[zz][c];
            const float s1 = sR[zz][C0 + c];
            const float s2 = sR[zz][2 * C0 + c];
            float4 h;
            h.x = tf32f(fmaf(s2, w2.x, fmaf(s1, w1.x, s0 * w0.x)));
            h.y = tf32f(fmaf(s2, w2.y, fmaf(s1, w1.y, s0 * w0.y)));
            h.z = tf32f(fmaf(s2, w2.z, fmaf(s1, w1.z, s0 * w0.z)));
            h.w = tf32f(fmaf(s2, w2.w, fmaf(s1, w1.w, s0 * w0.w)));
            *reinterpret_cast<float4*>(H + ((long long)(z0 + zz) * KH + r) * C1 + d4) = h;
        }
    }
}

// ---------------------------------------------------------------------------
// branch0_k: fully fused branch 0.
//   stage1: P = relu(pair @ w01 + b01)        (128x128 tile, K=256, BK=16)
//   stage2: X = relu(P @ w02 + b02)           (smem-resident, K=128, no syncs)
//   epi   : L0 = relu(X . w03 + b03)
// Dynamic smem union: stage1 As/Bs (40KB) overlap stage2 s1s (67.6KB);
// w02s (33.8KB) disjoint. Total 101.4KB -> 2 blocks/SM.
// ---------------------------------------------------------------------------
__global__ void __launch_bounds__(256, 2)
branch0_k(const float* __restrict__ sub, const float* __restrict__ W01,
          const float* __restrict__ b01, const float* __restrict__ W02,
          const float* __restrict__ b02, const float* __restrict__ w03,
          const float* __restrict__ b03, float* __restrict__ L0)
{
    constexpr int BM = 128, MT = 4, NT = 4;
    constexpr int nk = C0 / 16;   // 16

    extern __shared__ __align__(16) float sm[];
    float* AsF  = sm;                    // [2][128][SROW]
    float* BsF  = sm + 2 * 128 * SROW;   // [2][128][SROW]
    float* s1s  = sm;                    // [128][132] (stage2; reuses As/Bs region)
    float* w02s = sm + B0_W02_OFF;       // [64][132]

    const int tid = threadIdx.x, lane = tid & 31, wid = tid >> 5;
    const int lr = lane >> 2, lc = lane & 3;
    const int wm = (wid & 1) * 64;
    const int wn = (wid >> 1) * 32;
    const long long m0 = (long long)blockIdx.x * BM;

    // load w02 transposed + tf32-rounded (region disjoint from As/Bs)
    for (int idx = tid; idx < C1 * C2; idx += 256) {
        const int k = idx >> 6, n = idx & 63;
        w02s[n * 132 + k] = tf32f(W02[k * C2 + n]);
    }

    const int arow = tid & 127;
    const int ah   = tid >> 7;
    const int bd   = tid & 127;
    const int bh   = tid >> 7;

    const long long m = m0 + arow;
    const int pb = (int)(m / NN);
    const int pr = (int)(m - (long long)pb * NN);
    const int pi = pr / NTOK;
    const int pj = pr - pi * NTOK;
    const float* rowI = sub + (long long)(pb * NTOK + pi) * C0;
    const float* rowJ = sub + (long long)(pb * NTOK + pj) * C0;

    const unsigned aB = (unsigned)__cvta_generic_to_shared(AsF);
    const unsigned bB = (unsigned)__cvta_generic_to_shared(BsF);
    const unsigned aOff = ((lane & 7) + ((lane & 8) ? 8 : 0)) * (SROW * 4) + ((lane & 16) ? 16 : 0);
    const unsigned bOff = ((lane & 7) + ((lane & 16) ? 8 : 0)) * (SROW * 4) + ((lane & 8) ? 16 : 0);

    float aReg[8], bReg[8];
    float acc[MT][NT][4];
    #pragma unroll
    for (int mt = 0; mt < MT; mt++)
        #pragma unroll
        for (int nt = 0; nt < NT; nt++)
            #pragma unroll
            for (int c = 0; c < 4; c++) acc[mt][nt][c] = 0.f;

    auto loadA = [&](int kt) {
        const int k = kt * 16 + ah * 8;
        const float4 a0 = *reinterpret_cast<const float4*>(rowI + k);
        const float4 a1 = *reinterpret_cast<const float4*>(rowI + k + 4);
        const float4 b0 = *reinterpret_cast<const float4*>(rowJ + k);
        const float4 b1 = *reinterpret_cast<const float4*>(rowJ + k + 4);
        aReg[0] = a0.x * b0.x; aReg[1] = a0.y * b0.y; aReg[2] = a0.z * b0.z; aReg[3] = a0.w * b0.w;
        aReg[4] = a1.x * b1.x; aReg[5] = a1.y * b1.y; aReg[6] = a1.z * b1.z; aReg[7] = a1.w * b1.w;
    };
    auto loadB = [&](int kt) {
        const float* Wp = W01 + (kt * 16 + bh * 8) * C1 + bd;
        #pragma unroll
        for (int kk = 0; kk < 8; kk++) bReg[kk] = Wp[kk * C1];
    };
    auto stS = [&](int buf) {
        float* ap = AsF + buf * (128 * SROW) + arow * SROW + ah * 8;
        *reinterpret_cast<float4*>(ap) =
            make_float4(tf32f(aReg[0]), tf32f(aReg[1]), tf32f(aReg[2]), tf32f(aReg[3]));
        *reinterpret_cast<float4*>(ap + 4) =
            make_float4(tf32f(aReg[4]), tf32f(aReg[5]), tf32f(aReg[6]), tf32f(aReg[7]));
        float* bp = BsF + buf * (128 * SROW) + bd * SROW + bh * 8;
        *reinterpret_cast<float4*>(bp) =
            make_float4(tf32f(bReg[0]), tf32f(bReg[1]), tf32f(bReg[2]), tf32f(bReg[3]));
        *reinterpret_cast<float4*>(bp + 4) =
            make_float4(tf32f(bReg[4]), tf32f(bReg[5]), tf32f(bReg[6]), tf32f(bReg[7]));
    };

    loadA(0); loadB(0); stS(0);
    __syncthreads();

    for (int kt = 0; kt < nk; ++kt) {
        const int cur = kt & 1;
        if (kt + 1 < nk) { loadA(kt + 1); loadB(kt + 1); }
        const unsigned aBase = aB + cur * (128 * SROW * 4) + wm * (SROW * 4) + aOff;
        const unsigned bBase = bB + cur * (128 * SROW * 4) + wn * (SROW * 4) + bOff;
        #pragma unroll
        for (int ks = 0; ks < 2; ks++) {
            unsigned af[MT][4], bf[NT][2];
            #pragma unroll
            for (int mt = 0; mt < MT; mt++)
                ldsm4(af[mt][0], af[mt][1], af[mt][2], af[mt][3],
                      aBase + mt * 16 * SROW * 4 + ks * 32);
            #pragma unroll
            for (int g = 0; g < NT / 2; g++) {
                unsigned r0, r1, r2, r3;
                ldsm4(r0, r1, r2, r3, bBase + g * 16 * SROW * 4 + ks * 32);
                bf[2 * g][0] = r0; bf[2 * g][1] = r1;
                bf[2 * g + 1][0] = r2; bf[2 * g + 1][1] = r3;
            }
            #pragma unroll
            for (int mt = 0; mt < MT; mt++)
                #pragma unroll
                for (int nt = 0; nt < NT; nt++)
                    mma_tf32(acc[mt][nt], af[mt], bf[nt]);
        }
        if (kt + 1 < nk) stS(cur ^ 1);
        __syncthreads();
    }

    // stage1 epilogue -> s1s tile (tf32-rounded), overwrites As/Bs region
    #pragma unroll
    for (int mt = 0; mt < MT; mt++)
        #pragma unroll
        for (int nt = 0; nt < NT; nt++) {
            const int col = wn + nt * 8 + 2 * lc;
            #pragma unroll
            for (int h = 0; h < 2; h++) {
                const int row = wm + mt * 16 + lr + h * 8;
                const float v0 = tf32f(fmaxf(acc[mt][nt][2 * h]     + b01[col],     0.f));
                const float v1 = tf32f(fmaxf(acc[mt][nt][2 * h + 1] + b01[col + 1], 0.f));
                *reinterpret_cast<float2*>(&s1s[row * 132 + col]) = make_float2(v0, v1);
            }
        }
    __syncthreads();

    // stage2: X = s1s @ w02s  (M=128, N=64, K=128), warp tile 16x64, no syncs
    const unsigned s1B = (unsigned)__cvta_generic_to_shared(s1s);
    const unsigned wB  = (unsigned)__cvta_generic_to_shared(w02s);
    const unsigned aOff2 = ((lane & 7) + ((lane & 8) ? 8 : 0)) * 528 + ((lane & 16) ? 16 : 0);
    const unsigned bOff2 = ((lane & 7) + ((lane & 16) ? 8 : 0)) * 528 + ((lane & 8) ? 16 : 0);
    const int wm2 = wid * 16;

    float acc2[8][4];
    #pragma unroll
    for (int nt = 0; nt < 8; nt++)
        #pragma unroll
        for (int c = 0; c < 4; c++) acc2[nt][c] = 0.f;

    #pragma unroll
    for (int kt2 = 0; kt2 < 8; ++kt2) {
        #pragma unroll
        for (int ks = 0; ks < 2; ks++) {
            const unsigned colb = kt2 * 64 + ks * 32;
            unsigned af[4], bf[8][2];
            ldsm4(af[0], af[1], af[2], af[3], s1B + wm2 * 528 + aOff2 + colb);
            #pragma unroll
            for (int g = 0; g < 4; g++) {
                unsigned r0, r1, r2, r3;
                ldsm4(r0, r1, r2, r3, wB + bOff2 + g * 16 * 528 + colb);
                bf[2 * g][0] = r0; bf[2 * g][1] = r1;
                bf[2 * g + 1][0] = r2; bf[2 * g + 1][1] = r3;
            }
            #pragma unroll
            for (int nt = 0; nt < 8; nt++)
                mma_tf32(acc2[nt], af, bf[nt]);
        }
    }

    // epilogue: relu(+b02), dot w03, lane-group reduce, relu(+b03)
    float part0 = 0.f, part1 = 0.f;
    #pragma unroll
    for (int nt = 0; nt < 8; nt++) {
        const int col = nt * 8 + 2 * lc;
        const float w0 = w03[col], w1v = w03[col + 1];
        part0 += fmaxf(acc2[nt][0] + b02[col], 0.f) * w0
               + fmaxf(acc2[nt][1] + b02[col + 1], 0.f) * w1v;
        part1 += fmaxf(acc2[nt][2] + b02[col], 0.f) * w0
               + fmaxf(acc2[nt][3] + b02[col + 1], 0.f) * w1v;
    }
    part0 += __shfl_xor_sync(0xffffffffu, part0, 1);
    part0 += __shfl_xor_sync(0xffffffffu, part0, 2);
    part1 += __shfl_xor_sync(0xffffffffu, part1, 1);
    part1 += __shfl_xor_sync(0xffffffffu, part1, 2);
    if (lc == 0) {
        L0[m0 + wm2 + lr]     = fmaxf(part0 + b03[0], 0.f);
        L0[m0 + wm2 + lr + 8] = fmaxf(part1 + b03[0], 0.f);
    }
}

// ---------------------------------------------------------------------------
// conv1g2_k: conv1 GEMM from precomputed H. BK=16, BM=128 (j tile), BN=128.
// ---------------------------------------------------------------------------
__global__ void __launch_bounds__(256, 2)
conv1g2_k(const float* __restrict__ sub, const float* __restrict__ H,
          const float* __restrict__ bias, float* __restrict__ Out)
{
    constexpr int BM = 128, BN = 128, MT = 4, NT = 4;
    constexpr int nk = KH / 16;   // 48

    __shared__ __align__(16) float As[2][BM][SROW];
    __shared__ __align__(16) float Bs[2][BN][SROW];

    const int tid = threadIdx.x, lane = tid & 31, wid = tid >> 5;
    const int lr = lane >> 2, lc = lane & 3;
    const int wm = (wid & 1) * 64;
    const int wn = (wid >> 1) * 32;
    const int j0 = blockIdx.x * BM;
    const int z  = blockIdx.y;
    const int b  = z / NTOK;
    const int i  = z - b * NTOK;
    const float* subB = sub + (long long)b * NTOK * C0;
    const float* Hz   = H + (long long)z * KH * C1;

    const unsigned aB = (unsigned)__cvta_generic_to_shared(&As[0][0][0]);
    const unsigned bB = (unsigned)__cvta_generic_to_shared(&Bs[0][0][0]);
    const unsigned aOff = ((lane & 7) + ((lane & 8) ? 8 : 0)) * (SROW * 4) + ((lane & 16) ? 16 : 0);
    const unsigned bOff = ((lane & 7) + ((lane & 16) ? 8 : 0)) * (SROW * 4) + ((lane & 8) ? 16 : 0);

    const int arow = tid & 127;
    const int ah   = tid >> 7;          // 0/1 -> k offset 0/8
    const int bd   = tid & 127;
    const int bh   = tid >> 7;

    float aReg[8], bReg[8];
    float acc[MT][NT][4];
    #pragma unroll
    for (int mt = 0; mt < MT; mt++)
        #pragma unroll
        for (int nt = 0; nt < NT; nt++)
            #pragma unroll
            for (int c = 0; c < 4; c++) acc[mt][nt][c] = 0.f;

    auto loadA = [&](int kt) {
        const int kg = kt * 16 + ah * 8;
        const int q = kg >> 8;
        const int c = kg & 255;
        const int j = j0 + arow;
        const int jj = j + q - 1;
        if (j < NTOK && jj >= 0 && jj < NTOK) {
            const float4 v0 = *reinterpret_cast<const float4*>(subB + jj * C0 + c);
            const float4 v1 = *reinterpret_cast<const float4*>(subB + jj * C0 + c + 4);
            aReg[0] = v0.x; aReg[1] = v0.y; aReg[2] = v0.z; aReg[3] = v0.w;
            aReg[4] = v1.x; aReg[5] = v1.y; aReg[6] = v1.z; aReg[7] = v1.w;
        } else {
            #pragma unroll
            for (int c2 = 0; c2 < 8; c2++) aReg[c2] = 0.f;
        }
    };
    auto loadB = [&](int kt) {
        const float* Hp = Hz + (long long)(kt * 16 + bh * 8) * C1 + bd;
        #pragma unroll
        for (int kk = 0; kk < 8; kk++) bReg[kk] = Hp[kk * C1];
    };
    auto stS = [&](int buf) {
        *reinterpret_cast<float4*>(&As[buf][arow][ah * 8]) =
            make_float4(tf32f(aReg[0]), tf32f(aReg[1]), tf32f(aReg[2]), tf32f(aReg[3]));
        *reinterpret_cast<float4*>(&As[buf][arow][ah * 8 + 4]) =
            make_float4(tf32f(aReg[4]), tf32f(aReg[5]), tf32f(aReg[6]), tf32f(aReg[7]));
        *reinterpret_cast<float4*>(&Bs[buf][bd][bh * 8]) =
            make_float4(bReg[0], bReg[1], bReg[2], bReg[3]);   // H already tf32
        *reinterpret_cast<float4*>(&Bs[buf][bd][bh * 8 + 4]) =
            make_float4(bReg[4], bReg[5], bReg[6], bReg[7]);
    };

    loadA(0); loadB(0); stS(0);
    __syncthreads();

    for (int kt = 0; kt < nk; ++kt) {
        const int cur = kt & 1;
        if (kt + 1 < nk) { loadA(kt + 1); loadB(kt + 1); }
        const unsigned aBase = aB + cur * (BM * SROW * 4) + wm * (SROW * 4) + aOff;
        const unsigned bBase = bB + cur * (BN * SROW * 4) + wn * (SROW * 4) + bOff;
        #pragma unroll
        for (int ks = 0; ks < 2; ks++) {
            unsigned af[MT][4], bf[NT][2];
            #pragma unroll
            for (int mt = 0; mt < MT; mt++)
                ldsm4(af[mt][0], af[mt][1], af[mt][2], af[mt][3],
                      aBase + mt * 16 * SROW * 4 + ks * 32);
            #pragma unroll
            for (int g = 0; g < NT / 2; g++) {
                unsigned r0, r1, r2, r3;
                ldsm4(r0, r1, r2, r3, bBase + g * 16 * SROW * 4 + ks * 32);
                bf[2 * g][0] = r0; bf[2 * g][1] = r1;
                bf[2 * g + 1][0] = r2; bf[2 * g + 1][1] = r3;
            }
            #pragma unroll
            for (int mt = 0; mt < MT; mt++)
                #pragma unroll
                for (int nt = 0; nt < NT; nt++)
                    mma_tf32(acc[mt][nt], af[mt], bf[nt]);
        }
        if (kt + 1 < nk) stS(cur ^ 1);
        __syncthreads();
    }

    #pragma unroll
    for (int mt = 0; mt < MT; mt++)
        #pragma unroll
        for (int nt = 0; nt < NT; nt++) {
            const int col = wn + nt * 8 + 2 * lc;
            #pragma unroll
            for (int h = 0; h < 2; h++) {
                const int j = j0 + wm + mt * 16 + lr + h * 8;
                if (j >= NTOK) continue;
                const long long mm = (long long)b * NN + (long long)i * NTOK + j;
                float v0 = fmaxf(acc[mt][nt][2 * h]     + bias[col],     0.f);
                float v1 = fmaxf(acc[mt][nt][2 * h + 1] + bias[col + 1], 0.f);
                *reinterpret_cast<float2*>(Out + mm * C1 + col) = make_float2(v0, v1);
            }
        }
}

// ---------------------------------------------------------------------------
// conv24c_k: conv2 (128->64, W-dil=2) as single K=1152 implicit GEMM, BK=16.
// ---------------------------------------------------------------------------
__global__ void __launch_bounds__(256, 2)
conv24c_k(const float* __restrict__ In, const float* __restrict__ W,
          const float* __restrict__ bias, float* __restrict__ Out)
{
    constexpr int BM = 128, BN = 64, MT = 4, NT = 2;
    constexpr int nk = (9 * C1) / 16;   // 72

    __shared__ __align__(16) float As[2][BM][SROW];
    __shared__ __align__(16) float Bs[2][BN][SROW];
    __shared__ int rowbase[9][BM];

    const int tid = threadIdx.x, lane = tid & 31, wid = tid >> 5;
    const int lr = lane >> 2, lc = lane & 3;
    const int wm = (wid & 1) * 64;
    const int wn = (wid >> 1) * 16;
    const int m0 = blockIdx.x * BM;

    if (tid < BM) {
        const int m = m0 + tid;
        const int pb = m / NN;
        const int r = m - pb * NN;
        const int pi = r / NTOK;
        const int pj = r - pi * NTOK;
        #pragma unroll
        for (int tap = 0; tap < 9; tap++) {
            const int p = tap / 3 - 1, q = tap % 3 - 1;
            const int ii = pi + p, jj = pj + q * 2;
            rowbase[tap][tid] = (ii >= 0 && ii < NTOK && jj >= 0 && jj < NTOK)
                              ? ((pb * NTOK + ii) * NTOK + jj) * C1 : -1;
        }
    }
    __syncthreads();

    const unsigned aB = (unsigned)__cvta_generic_to_shared(&As[0][0][0]);
    const unsigned bB = (unsigned)__cvta_generic_to_shared(&Bs[0][0][0]);
    const unsigned aOff = ((lane & 7) + ((lane & 8) ? 8 : 0)) * (SROW * 4) + ((lane & 16) ? 16 : 0);
    const unsigned bOff = ((lane & 7) + ((lane & 16) ? 8 : 0)) * (SROW * 4) + ((lane & 8) ? 16 : 0);

    const int arow = tid & 127;
    const int ah   = tid >> 7;          // 0/1
    const int bd   = tid & 63;
    const int bg   = tid >> 6;          // 0..3 -> 4 k each

    float aReg[8], bReg[4];
    float acc[MT][NT][4];
    #pragma unroll
    for (int mt = 0; mt < MT; mt++)
        #pragma unroll
        for (int nt = 0; nt < NT; nt++)
            #pragma unroll
            for (int c = 0; c < 4; c++) acc[mt][nt][c] = 0.f;

    auto loadA = [&](int kt) {
        const int kg = kt * 16 + ah * 8;
        const int tap = kg >> 7;
        const int c = kg & 127;
        const int base = rowbase[tap][arow];
        if (base >= 0) {
            const float4 v0 = *reinterpret_cast<const float4*>(In + base + c);
            const float4 v1 = *reinterpret_cast<const float4*>(In + base + c + 4);
            aReg[0] = v0.x; aReg[1] = v0.y; aReg[2] = v0.z; aReg[3] = v0.w;
            aReg[4] = v1.x; aReg[5] = v1.y; aReg[6] = v1.z; aReg[7] = v1.w;
        } else {
            #pragma unroll
            for (int c2 = 0; c2 < 8; c2++) aReg[c2] = 0.f;
        }
    };
    auto loadB = [&](int kt) {
        #pragma unroll
        for (int kk = 0; kk < 4; kk++) {
            const int kg = kt * 16 + bg * 4 + kk;
            const int tap = kg >> 7;
            const int c = kg & 127;
            bReg[kk] = W[((size_t)(tap * C1 + c)) * C2 + bd];
        }
    };
    auto stS = [&](int buf) {
        *reinterpret_cast<float4*>(&As[buf][arow][ah * 8]) =
            make_float4(tf32f(aReg[0]), tf32f(aReg[1]), tf32f(aReg[2]), tf32f(aReg[3]));
        *reinterpret_cast<float4*>(&As[buf][arow][ah * 8 + 4]) =
            make_float4(tf32f(aReg[4]), tf32f(aReg[5]), tf32f(aReg[6]), tf32f(aReg[7]));
        *reinterpret_cast<float4*>(&Bs[buf][bd][bg * 4]) =
            make_float4(tf32f(bReg[0]), tf32f(bReg[1]), tf32f(bReg[2]), tf32f(bReg[3]));
    };

    loadA(0); loadB(0); stS(0);
    __syncthreads();

    for (int kt = 0; kt < nk; ++kt) {
        const int cur = kt & 1;
        if (kt + 1 < nk) { loadA(kt + 1); loadB(kt + 1); }
        const unsigned aBase = aB + cur * (BM * SROW * 4) + wm * (SROW * 4) + aOff;
        const unsigned bBase = bB + cur * (BN * SROW * 4) + wn * (SROW * 4) + bOff;
        #pragma unroll
        for (int ks = 0; ks < 2; ks++) {
            unsigned af[MT][4], bf[NT][2];
            #pragma unroll
            for (int mt = 0; mt < MT; mt++)
                ldsm4(af[mt][0], af[mt][1], af[mt][2], af[mt][3],
                      aBase + mt * 16 * SROW * 4 + ks * 32);
            {
                unsigned r0, r1, r2, r3;
                ldsm4(r0, r1, r2, r3, bBase + ks * 32);
                bf[0][0] = r0; bf[0][1] = r1;
                bf[1][0] = r2; bf[1][1] = r3;
            }
            #pragma unroll
            for (int mt = 0; mt < MT; mt++)
                #pragma unroll
                for (int nt = 0; nt < NT; nt++)
                    mma_tf32(acc[mt][nt], af[mt], bf[nt]);
        }
        if (kt + 1 < nk) stS(cur ^ 1);
        __syncthreads();
    }

    #pragma unroll
    for (int mt = 0; mt < MT; mt++)
        #pragma unroll
        for (int nt = 0; nt < NT; nt++) {
            const int col = wn + nt * 8 + 2 * lc;
            #pragma unroll
            for (int h = 0; h < 2; h++) {
                const long long row = m0 + wm + mt * 16 + lr + h * 8;
                float v0 = fmaxf(acc[mt][nt][2 * h]     + bias[col],     0.f);
                float v1 = fmaxf(acc[mt][nt][2 * h + 1] + bias[col + 1], 0.f);
                *reinterpret_cast<float2*>(Out + row * C2 + col) = make_float2(v0, v1);
            }
        }
}

// ---------------------------------------------------------------------------
// Last conv (64 -> 1, dil 4): one warp per output pixel.
// ---------------------------------------------------------------------------
template<int CIN, int DILW>
__global__ void convlast_k(const float* __restrict__ In, const float* __restrict__ W,
                           const float* __restrict__ bias, float* __restrict__ Out)
{
    const int lane = threadIdx.x & 31;
    const int wp   = threadIdx.x >> 5;
    const int m    = blockIdx.x * 8 + wp;
    const int b = m / NN;
    const int r = m - b * NN;
    const int i = r / NTOK;
    const int j = r - i * NTOK;
    float acc = 0.f;
    #pragma unroll
    for (int tap = 0; tap < 9; ++tap) {
        const int p = tap / 3 - 1, q = tap % 3 - 1;
        const int ii = i + p, jj = j + q * DILW;
        if (ii >= 0 && ii < NTOK && jj >= 0 && jj < NTOK) {
            const float* src = In + (long long)((b * NTOK + ii) * NTOK + jj) * CIN;
            const float* w   = W + tap * CIN;
            acc = fmaf(src[lane],      w[lane],      acc);
            acc = fmaf(src[lane + 32], w[lane + 32], acc);
        }
    }
    #pragma unroll
    for (int off = 16; off; off >>= 1) acc += __shfl_xor_sync(0xffffffffu, acc, off);
    if (lane == 0) Out[m] = fmaxf(acc + bias[0], 0.f);
}

// softmax stats over symmetrized logits, per batch
__global__ void smax_stats_k()
{
    const int b = blockIdx.x;
    const float* Lb = (blockIdx.y ? g_L1 : g_L0) + b * NN;
    __shared__ float red[256];
    const int tid = threadIdx.x;
    float mx = -1e30f;
    for (int idx = tid; idx < NN; idx += 256) {
        const int i = idx / NTOK, j = idx - (idx / NTOK) * NTOK;
        mx = fmaxf(mx, Lb[idx] + Lb[j * NTOK + i]);
    }
    red[tid] = mx; __syncthreads();
    for (int s = 128; s; s >>= 1) {
        if (tid < s) red[tid] = fmaxf(red[tid], red[tid + s]);
        __syncthreads();
    }
    mx = red[0]; __syncthreads();
    float sum = 0.f;
    for (int idx = tid; idx < NN; idx += 256) {
        const int i = idx / NTOK, j = idx - (idx / NTOK) * NTOK;
        sum += expf(Lb[idx] + Lb[j * NTOK + i] - mx);
    }
    red[tid] = sum; __syncthreads();
    for (int s = 128; s; s >>= 1) {
        if (tid < s) red[tid] += red[tid + s];
        __syncthreads();
    }
    if (tid == 0) {
        g_stats[(blockIdx.y * 8 + b) * 2]     = mx;
        g_stats[(blockIdx.y * 8 + b) * 2 + 1] = red[0];
    }
}

// Mc = 0.5 * (softmax0 + softmax1)
__global__ void combine_k()
{
    const int idx = blockIdx.x * 256 + threadIdx.x;
    if (idx >= MTOT) return;
    const int b = idx / NN;
    const int r = idx - b * NN;
    const int i = r / NTOK;
    const int j = r - i * NTOK;
    const int t = b * NN + j * NTOK + i;
    const float s0 = g_L0[idx] + g_L0[t];
    const float s1 = g_L1[idx] + g_L1[t];
    const float m0 = g_stats[b * 2],      z0 = g_stats[b * 2 + 1];
    const float m1 = g_stats[16 + b * 2], z1 = g_stats[16 + b * 2 + 1];
    g_Mc[idx] = 0.5f * (expf(s0 - m0) / z0 + expf(s1 - m1) / z1);
}

// ---------------------------------------------------------------------------
extern "C" void kernel_launch(void* const* d_in, const int* in_sizes, int n_in,
                              void* d_out, int out_size)
{
    (void)in_sizes; (void)n_in; (void)out_size;
    const float* x     = (const float*)d_in[0];
    const float* w_prj = (const float*)d_in[1];
    const float* b_prj = (const float*)d_in[2];
    const float* w01   = (const float*)d_in[3];
    const float* b01   = (const float*)d_in[4];
    const float* w02   = (const float*)d_in[5];
    const float* b02   = (const float*)d_in[6];
    const float* w03   = (const float*)d_in[7];
    const float* b03   = (const float*)d_in[8];
    const float* w1    = (const float*)d_in[9];
    const float* b1    = (const float*)d_in[10];
    const float* w2    = (const float*)d_in[11];
    const float* b2    = (const float*)d_in[12];
    const float* w3    = (const float*)d_in[13];
    const float* b3    = (const float*)d_in[14];
    float* out = (float*)d_out;

    float *sub, *s1, *s2, *H, *L0, *L1, *Mc;
    cudaGetSymbolAddress((void**)&sub,  g_sub);
    cudaGetSymbolAddress((void**)&s1,   g_s1);
    cudaGetSymbolAddress((void**)&s2,   g_s2);
    cudaGetSymbolAddress((void**)&H,    g_H);
    cudaGetSymbolAddress((void**)&L0,   g_L0);
    cudaGetSymbolAddress((void**)&L1,   g_L1);
    cudaGetSymbolAddress((void**)&Mc,   g_Mc);

    static bool attr_set = false;
    if (!attr_set) {
        cudaFuncSetAttribute(branch0_k, cudaFuncAttributeMaxDynamicSharedMemorySize,
                             B0_SMEM_FLOATS * 4);
        attr_set = true;
    }

    // 1. projection
    gemm_tc<false, true><<<dim3(13, 2, 1), 256>>>(
        x, w_prj, b_prj, sub, NBATCH * NTOK, INDIM, C0, 0, 0, 0);

    // 2. H factor build
    hbuild_k<<<NBATCH * NTOK / 8, 256>>>(sub, w1, H);

    // 3. branch 0 fully fused -> L0
    branch0_k<<<MTOT / 128, 256, B0_SMEM_FLOATS * 4>>>(
        sub, w01, b01, w02, b02, w03, b03, L0);

    // 4. branch 1
    conv1g2_k<<<dim3(2, NBATCH * NTOK), 256>>>(sub, H, b1, s1);
    conv24c_k<<<MTOT / 128, 256>>>(s1, w2, b2, s2);
    convlast_k<64, 4><<<MTOT / 8, 256>>>(s2, w3, b3, L1);

    // 5. softmax + combine
    smax_stats_k<<<dim3(8, 2), 256>>>();
    combine_k<<<(MTOT + 255) / 256, 256>>>();

    // 6. aggregation
    gemm_tc<false, false><<<dim3(2, 16, 8), 256>>>(
        Mc, x, nullptr, out, NTOK, NTOK, INDIM,
        (long long)NN, (long long)NTOK * INDIM, (long long)NTOK * INDIM);
}